// round 4
// baseline (speedup 1.0000x reference)
#include <cuda_runtime.h>

// Fused: QKV proj -> 4-head attention (S=32, D=32) -> out proj -> residual -> LayerNorm
// E=128, S=32, H=4, D=32. BB=2 batches per CTA => 64x128 row tile.
// fp32 everywhere; GEMMs use packed fma.rn.f32x2 (SIMD over K pairs).

#define TE 128
#define TS 32
#define TH 4
#define TD 32
#define BB 2
#define RR 64          // BB*TS rows per CTA
#define NT 256
#define KF 32          // float4 slots per 128-float row

typedef unsigned long long u64;

// smem floats: x(64*128) + q + k + v + w(128*128) = 4*8192 + 16384 = 49152 floats
#define SMEM_BYTES (49152 * 4)

__device__ __forceinline__ void fma2(u64 &acc, u64 a, u64 b) {
    asm("fma.rn.f32x2 %0, %1, %2, %0;" : "+l"(acc) : "l"(a), "l"(b));
}
__device__ __forceinline__ float2 asf2(u64 v) {
    float2 r;
    asm("mov.b64 {%0, %1}, %2;" : "=f"(r.x), "=f"(r.y) : "l"(v));
    return r;
}
__device__ __forceinline__ float wredsum(float v) {
#pragma unroll
    for (int o = 16; o; o >>= 1) v += __shfl_xor_sync(0xffffffffu, v, o);
    return v;
}
__device__ __forceinline__ float wredmax(float v) {
#pragma unroll
    for (int o = 16; o; o >>= 1) v = fmaxf(v, __shfl_xor_sync(0xffffffffu, v, o));
    return v;
}

// Load W [128x128] row-major into smem, XOR-swizzled at float4 granularity:
// slot for column-float4 c of row f is (c ^ (f>>2)). Coalesced global reads,
// conflict-free STS.128 (per-warp: one f, c = lane -> permutation).
__device__ __forceinline__ void load_weight(float4* ws4, const float* __restrict__ W, int tid) {
    const float4* gw = (const float4*)W;
#pragma unroll
    for (int p = 0; p < 16; ++p) {
        int e = p * NT + tid;          // 0..4095
        int f = e >> 5;
        int c = e & 31;
        ws4[f * KF + (c ^ (f >> 2))] = gw[e];
    }
}

// C[64][128] = src @ W^T  (both operands K-major in smem, swizzled).
// Thread (warp w, lane tx): rows r0=w*8 .. r0+7, cols f = tx*4 .. tx*4+3.
// Accumulate in f32x2 pairs over K (even/odd k lanes), reduce at the end.
__device__ __forceinline__ void gemm_acc(const float4* __restrict__ src4,
                                         const float4* __restrict__ ws4,
                                         int r0, int tx, float out[8][4]) {
    u64 acc[8][4];
#pragma unroll
    for (int i = 0; i < 8; ++i)
#pragma unroll
        for (int j = 0; j < 4; ++j) acc[i][j] = 0ull;

#pragma unroll 4
    for (int k4 = 0; k4 < 32; ++k4) {
        ulonglong2 a[8];
#pragma unroll
        for (int i = 0; i < 8; ++i) {
            int r = r0 + i;
            a[i] = *reinterpret_cast<const ulonglong2*>(&src4[r * KF + (k4 ^ (r & 31))]);
        }
        ulonglong2 b[4];
#pragma unroll
        for (int j = 0; j < 4; ++j) {
            int f = tx * 4 + j;
            b[j] = *reinterpret_cast<const ulonglong2*>(&ws4[f * KF + (k4 ^ tx)]);
        }
#pragma unroll
        for (int i = 0; i < 8; ++i)
#pragma unroll
            for (int j = 0; j < 4; ++j) {
                fma2(acc[i][j], a[i].x, b[j].x);
                fma2(acc[i][j], a[i].y, b[j].y);
            }
    }
#pragma unroll
    for (int i = 0; i < 8; ++i)
#pragma unroll
        for (int j = 0; j < 4; ++j) {
            float2 t = asf2(acc[i][j]);
            out[i][j] = t.x + t.y;
        }
}

__global__ void __launch_bounds__(NT, 1)
fused_attn_kernel(const float* __restrict__ inputs,
                  const float* __restrict__ Wq, const float* __restrict__ bq,
                  const float* __restrict__ Wk, const float* __restrict__ bk,
                  const float* __restrict__ Wv, const float* __restrict__ bv,
                  const float* __restrict__ Wo, const float* __restrict__ bo,
                  const float* __restrict__ gamma, const float* __restrict__ beta,
                  float* __restrict__ out)
{
    extern __shared__ float smem[];
    float4* xs4 = (float4*)smem;
    float4* qs4 = xs4 + RR * KF;
    float4* ks4 = qs4 + RR * KF;
    float4* vs4 = ks4 + RR * KF;
    float4* ws4 = vs4 + RR * KF;

    const int tid  = threadIdx.x;
    const int lane = tid & 31;
    const int warp = tid >> 5;
    const int r0   = warp * 8;
    const int tx   = lane;

    // ---- load x tile (swizzled) ----
    const float4* gx = (const float4*)inputs + (size_t)blockIdx.x * (RR * KF);
#pragma unroll
    for (int p = 0; p < (RR * KF) / NT; ++p) {   // 8 passes
        int e = p * NT + tid;
        int r = e >> 5;
        int c = e & 31;
        xs4[r * KF + (c ^ (r & 31))] = gx[e];
    }
    load_weight(ws4, Wq, tid);
    __syncthreads();

    float res[8][4];
    const float qscale = 0.17677669529663687f;   // 1/sqrt(32)

    // ---- Q = (x @ Wq^T + bq) * qscale ----
    gemm_acc(xs4, ws4, r0, tx, res);
    {
        float4 b4 = ((const float4*)bq)[tx];
#pragma unroll
        for (int i = 0; i < 8; ++i) {
            int r = r0 + i;
            float4 o;
            o.x = (res[i][0] + b4.x) * qscale;
            o.y = (res[i][1] + b4.y) * qscale;
            o.z = (res[i][2] + b4.z) * qscale;
            o.w = (res[i][3] + b4.w) * qscale;
            qs4[r * KF + (tx ^ (r & 31))] = o;
        }
    }
    __syncthreads();
    load_weight(ws4, Wk, tid);
    __syncthreads();

    // ---- K ----
    gemm_acc(xs4, ws4, r0, tx, res);
    {
        float4 b4 = ((const float4*)bk)[tx];
#pragma unroll
        for (int i = 0; i < 8; ++i) {
            int r = r0 + i;
            float4 o;
            o.x = res[i][0] + b4.x;
            o.y = res[i][1] + b4.y;
            o.z = res[i][2] + b4.z;
            o.w = res[i][3] + b4.w;
            ks4[r * KF + (tx ^ (r & 31))] = o;
        }
    }
    __syncthreads();
    load_weight(ws4, Wv, tid);
    __syncthreads();

    // ---- V ----
    gemm_acc(xs4, ws4, r0, tx, res);
    {
        float4 b4 = ((const float4*)bv)[tx];
#pragma unroll
        for (int i = 0; i < 8; ++i) {
            int r = r0 + i;
            float4 o;
            o.x = res[i][0] + b4.x;
            o.y = res[i][1] + b4.y;
            o.z = res[i][2] + b4.z;
            o.w = res[i][3] + b4.w;
            vs4[r * KF + (tx ^ (r & 31))] = o;
        }
    }
    __syncthreads();

    // ws free now; preload Wo while attention runs (attention never touches ws)
    load_weight(ws4, Wo, tid);

    // ---- attention: warp = (batch bb, head h); ctx overwrites q in-place ----
    {
        const int bb    = warp >> 2;       // 0..1
        const int h     = warp & 3;        // 0..3
        const int rbase = bb * 32;
        const int c4b   = h * 8;           // float4 col base of this head

        float kreg[32], vreg[32];
        // K row t = lane, all 32 d values
        {
            int rk = rbase + lane;
#pragma unroll
            for (int c = 0; c < 8; ++c) {
                float4 kv = ks4[rk * KF + ((c4b + c) ^ (rk & 31))];
                kreg[c * 4 + 0] = kv.x; kreg[c * 4 + 1] = kv.y;
                kreg[c * 4 + 2] = kv.z; kreg[c * 4 + 3] = kv.w;
            }
        }
        // V column d = lane, all 32 t values (scalar gathers, conflict-free by swizzle)
        {
            const float* vsf = (const float*)vs4;
            int cslot = c4b + (lane >> 2);
            int sub = lane & 3;
#pragma unroll
            for (int t = 0; t < 32; ++t) {
                int r = rbase + t;
                vreg[t] = vsf[r * TE + ((cslot ^ (r & 31)) << 2) + sub];
            }
        }

        float* qsf = (float*)qs4;
        const int cslot = c4b + (lane >> 2);
        const int sub = lane & 3;
#pragma unroll 1
        for (int s = 0; s < 32; ++s) {
            int rq = rbase + s;
            // score(s, t=lane) = q[s,:] . k[t,:]
            float sc = 0.f;
#pragma unroll
            for (int c = 0; c < 8; ++c) {
                float4 qv = qs4[rq * KF + ((c4b + c) ^ (rq & 31))];  // broadcast
                sc = fmaf(qv.x, kreg[c * 4 + 0],
                     fmaf(qv.y, kreg[c * 4 + 1],
                     fmaf(qv.z, kreg[c * 4 + 2],
                     fmaf(qv.w, kreg[c * 4 + 3], sc))));
            }
            float m = wredmax(sc);
            float p = __expf(sc - m);
            float psum = wredsum(p);
            p = p / psum;
            // ctx[s, d=lane] = sum_t p_t * v[t, d]
            float ctx = 0.f;
#pragma unroll
            for (int t = 0; t < 32; ++t)
                ctx = fmaf(__shfl_sync(0xffffffffu, p, t), vreg[t], ctx);
            // overwrite q row s (done being read) with ctx
            qsf[rq * TE + ((cslot ^ (rq & 31)) << 2) + sub] = ctx;
        }
    }
    __syncthreads();

    // ---- out = ctx @ Wo^T + bo + x, then LayerNorm ----
    gemm_acc(qs4, ws4, r0, tx, res);
    {
        float4 b4  = ((const float4*)bo)[tx];
        float4 g4  = ((const float4*)gamma)[tx];
        float4 be4 = ((const float4*)beta)[tx];
        float4* gout = (float4*)out + (size_t)blockIdx.x * (RR * KF);
#pragma unroll
        for (int i = 0; i < 8; ++i) {
            int r = r0 + i;
            float4 xr = xs4[r * KF + (tx ^ (r & 31))];
            float ox = res[i][0] + b4.x + xr.x;
            float oy = res[i][1] + b4.y + xr.y;
            float oz = res[i][2] + b4.z + xr.z;
            float ow = res[i][3] + b4.w + xr.w;
            float mu = wredsum(ox + oy + oz + ow) * (1.f / 128.f);
            float dx = ox - mu, dy = oy - mu, dz = oz - mu, dw = ow - mu;
            float var = wredsum(dx * dx + dy * dy + dz * dz + dw * dw) * (1.f / 128.f);
            float rstd = rsqrtf(var + 1e-5f);
            float4 w;
            w.x = dx * rstd * g4.x + be4.x;
            w.y = dy * rstd * g4.y + be4.y;
            w.z = dz * rstd * g4.z + be4.z;
            w.w = dw * rstd * g4.w + be4.w;
            gout[r * KF + tx] = w;
        }
    }
}

extern "C" void kernel_launch(void* const* d_in, const int* in_sizes, int n_in,
                              void* d_out, int out_size) {
    const float* inputs = (const float*)d_in[0];
    const float* Wq = (const float*)d_in[1];
    const float* bq = (const float*)d_in[2];
    const float* Wk = (const float*)d_in[3];
    const float* bk = (const float*)d_in[4];
    const float* Wv = (const float*)d_in[5];
    const float* bv = (const float*)d_in[6];
    const float* Wo = (const float*)d_in[7];
    const float* bo = (const float*)d_in[8];
    const float* gamma = (const float*)d_in[9];
    const float* beta  = (const float*)d_in[10];
    float* outp = (float*)d_out;

    int B = in_sizes[0] / 4096;           // 16384
    int grid = B / BB;                    // 8192

    cudaFuncSetAttribute(fused_attn_kernel,
                         cudaFuncAttributeMaxDynamicSharedMemorySize, SMEM_BYTES);
    fused_attn_kernel<<<grid, NT, SMEM_BYTES>>>(inputs, Wq, bq, Wk, bk, Wv, bv,
                                                Wo, bo, gamma, beta, outp);
}

// round 6
// speedup vs baseline: 1.6322x; 1.6322x over previous
#include <cuda_runtime.h>
#include <cuda_bf16.h>
#include <cstdint>

// Fused SelfAttention via warp-level bf16 mma.sync (HMMA path; tcgen05 is not
// available at the harness's sm_103 virtual target).
// E=128, S=32, H=4, D=32. CTA = 64 rows (2 batches), 256 threads, grid 8192.
// GEMMs: C = Ahi@Whi + Alo@Whi + Ahi@Wlo  (bf16 split, fp32 accum, err ~2^-16).
//
// SMEM bytes:
//   A   @0       : 64 rows x 512B   (bf16 [64][256]: k 0-127 = hi, 128-255 = lo)
//   W   @32768   : 128 rows x 512B  (bf16 [128][256]: Whi | Wlo), swizzled image
//   Q   @98304   : fp32 [64][128] swizzled (float4 slot ^ (row&31))
//   K   @131072  : fp32 [64][128]
//   V   @163840  : fp32 [64][128]
//   LN partials reuse Q region.

typedef unsigned int u32;

#define NT 256
#define AOFF 0
#define WOFF 32768
#define QOFF 98304
#define KOFF 131072
#define VOFF 163840
#define SMEM_BYTES 196608
#define QSCALE 0.17677669529663687f

// 4 weights x 64KB swizzled-SMEM-image of bf16 [128][256]
__device__ __align__(16) unsigned char g_Wpk[262144];

// ---------------- prep kernel: split W into bf16 hi/lo smem images ----------------
__global__ void prep_split(const float* __restrict__ Wq, const float* __restrict__ Wk,
                           const float* __restrict__ Wv, const float* __restrict__ Wo) {
    int id = blockIdx.x * blockDim.x + threadIdx.x;   // 0..65535 (u32 words)
    const float* W = (id < 16384) ? Wq : (id < 32768) ? Wk : (id < 49152) ? Wv : Wo;
    int rem = id & 16383;
    int f = rem >> 7;          // row 0..127
    int w = rem & 127;         // u32 word within 512B row
    int pc = w >> 2, j = w & 3;
    int lc = pc ^ (f & 7);     // logical 16B chunk
    int k0 = lc * 8 + j * 2;   // logical bf16 col (0..255)
    __nv_bfloat16 v[2];
#pragma unroll
    for (int i = 0; i < 2; ++i) {
        int kc = k0 + i;
        if (kc < 128) {
            v[i] = __float2bfloat16_rn(W[f * 128 + kc]);
        } else {
            float x = W[f * 128 + (kc - 128)];
            __nv_bfloat16 h = __float2bfloat16_rn(x);
            v[i] = __float2bfloat16_rn(x - __bfloat162float(h));
        }
    }
    __nv_bfloat162 p = __halves2bfloat162(v[0], v[1]);
    ((u32*)g_Wpk)[id] = *(u32*)&p;
}

// ---------------- helpers ----------------
__device__ __forceinline__ u32 s2u(const void* p) {
    u32 a;
    asm("{ .reg .u64 t; cvta.to.shared.u64 t, %1; cvt.u32.u64 %0, t; }" : "=r"(a) : "l"(p));
    return a;
}
__device__ __forceinline__ void ldsm4(u32& r0, u32& r1, u32& r2, u32& r3, u32 a) {
    asm volatile("ldmatrix.sync.aligned.m8n8.x4.shared.b16 {%0,%1,%2,%3}, [%4];"
                 : "=r"(r0), "=r"(r1), "=r"(r2), "=r"(r3) : "r"(a));
}
__device__ __forceinline__ void mma16816(float* c, u32 a0, u32 a1, u32 a2, u32 a3,
                                         u32 b0, u32 b1) {
    asm volatile(
        "mma.sync.aligned.m16n8k16.row.col.f32.bf16.bf16.f32 "
        "{%0,%1,%2,%3}, {%4,%5,%6,%7}, {%8,%9}, {%0,%1,%2,%3};"
        : "+f"(c[0]), "+f"(c[1]), "+f"(c[2]), "+f"(c[3])
        : "r"(a0), "r"(a1), "r"(a2), "r"(a3), "r"(b0), "r"(b1));
}
__device__ __forceinline__ u32 pkbf(float a, float b) {
    __nv_bfloat162 t = __halves2bfloat162(__float2bfloat16_rn(a), __float2bfloat16_rn(b));
    return *(u32*)&t;
}

// C[m0..+15][n0..+63] += A(64x384 logical) @ W^T ; both bf16 swizzled images.
__device__ __forceinline__ void run_gemm(u32 smA, u32 smW, int m0, int n0, int lane,
                                         float acc[8][4]) {
    int arow = m0 + (lane & 7) + ((lane & 8) ? 8 : 0);
    u32 aRow = smA + arow * 512;
    const int asw = arow & 7;
    const int acs = lane >> 4;          // +0/+1 chunk (k lo/hi 8)
    u32 bRow[4]; int bsw[4];
#pragma unroll
    for (int nt = 0; nt < 4; ++nt) {
        int brow = n0 + nt * 16 + (lane & 7) + ((lane & 16) ? 8 : 0);
        bRow[nt] = smW + brow * 512;
        bsw[nt] = brow & 7;
    }
    const int bcs = (lane >> 3) & 1;
#pragma unroll
    for (int i = 0; i < 8; ++i)
#pragma unroll
        for (int j = 0; j < 4; ++j) acc[i][j] = 0.f;

#pragma unroll
    for (int seg = 0; seg < 3; ++seg) {
        const int ab = (seg == 1) ? 16 : 0;   // A lo chunks for seg1
        const int bb = (seg == 2) ? 16 : 0;   // W lo chunks for seg2
#pragma unroll
        for (int j = 0; j < 8; ++j) {
            u32 a0, a1, a2, a3;
            int ach = ab + 2 * j + acs;
            ldsm4(a0, a1, a2, a3, aRow + ((ach ^ asw) << 4));
            int bch = bb + 2 * j + bcs;
#pragma unroll
            for (int nt = 0; nt < 4; ++nt) {
                u32 b0, b1, b2, b3;
                ldsm4(b0, b1, b2, b3, bRow[nt] + ((bch ^ bsw[nt]) << 4));
                mma16816(acc[2 * nt],     a0, a1, a2, a3, b0, b1);
                mma16816(acc[2 * nt + 1], a0, a1, a2, a3, b2, b3);
            }
        }
    }
}

// store acc frags into fp32 swizzled [64][128] buffer
__device__ __forceinline__ void store_qkv(float* dst, const float acc[8][4],
                                          int m0, int n0, int lane) {
    const int r1 = m0 + (lane >> 2), r2 = r1 + 8;
#pragma unroll
    for (int nt = 0; nt < 8; ++nt) {
        int c = n0 + nt * 8 + (lane & 3) * 2;
        int slot = c >> 2, cr = c & 3;
        *(float2*)(dst + r1 * 128 + ((slot ^ (r1 & 31)) << 2) + cr) =
            make_float2(acc[nt][0], acc[nt][1]);
        *(float2*)(dst + r2 * 128 + ((slot ^ (r2 & 31)) << 2) + cr) =
            make_float2(acc[nt][2], acc[nt][3]);
    }
}

__device__ __forceinline__ void fillW(char* sm, int g, int tid) {
    const uint4* src = (const uint4*)g_Wpk + g * 4096;
    uint4* dst = (uint4*)(sm + WOFF);
#pragma unroll
    for (int p = 0; p < 16; ++p) dst[p * NT + tid] = __ldg(src + p * NT + tid);
}

// ---------------- main kernel ----------------
__global__ void __launch_bounds__(NT, 1)
fused_attn_mma(const float* __restrict__ inputs,
               const float* __restrict__ bq, const float* __restrict__ bk,
               const float* __restrict__ bv, const float* __restrict__ bo,
               const float* __restrict__ gamma, const float* __restrict__ beta,
               float* __restrict__ outp)
{
    extern __shared__ char sm[];
    const int tid = threadIdx.x;
    const int lane = tid & 31;
    const int warp = tid >> 5;
    const u32 smb = s2u(sm);
    const u32 smA = smb + AOFF, smW = smb + WOFF;
    const int m0 = (warp & 3) * 16;
    const int n0 = (warp >> 2) * 64;
    const size_t tbase = (size_t)blockIdx.x * 8192;

    // ---- fill A (x split hi/lo) + Wq ----
    {
        const float4* gx = (const float4*)(inputs + tbase);
#pragma unroll
        for (int p = 0; p < 8; ++p) {
            int e = p * NT + tid;
            int row = e >> 5, c4 = e & 31;
            float4 v = __ldg(gx + e);
            float hx = __bfloat162float(__float2bfloat16_rn(v.x));
            float hy = __bfloat162float(__float2bfloat16_rn(v.y));
            float hz = __bfloat162float(__float2bfloat16_rn(v.z));
            float hw = __bfloat162float(__float2bfloat16_rn(v.w));
            uint2 hi = make_uint2(pkbf(v.x, v.y), pkbf(v.z, v.w));
            uint2 lo = make_uint2(pkbf(v.x - hx, v.y - hy), pkbf(v.z - hz, v.w - hw));
            char* arow = sm + AOFF + row * 512;
            int ch = c4 >> 1, off8 = (c4 & 1) * 8, sw = row & 7;
            *(uint2*)(arow + ((ch ^ sw) << 4) + off8) = hi;
            *(uint2*)(arow + (((16 + ch) ^ sw) << 4) + off8) = lo;
        }
    }
    fillW(sm, 0, tid);
    __syncthreads();

    float acc[8][4];

    // ---- Q ----
    run_gemm(smA, smW, m0, n0, lane, acc);
    store_qkv((float*)(sm + QOFF), acc, m0, n0, lane);
    __syncthreads();
    fillW(sm, 1, tid);
    __syncthreads();
    // ---- K ----
    run_gemm(smA, smW, m0, n0, lane, acc);
    store_qkv((float*)(sm + KOFF), acc, m0, n0, lane);
    __syncthreads();
    fillW(sm, 2, tid);
    __syncthreads();
    // ---- V ----
    run_gemm(smA, smW, m0, n0, lane, acc);
    store_qkv((float*)(sm + VOFF), acc, m0, n0, lane);
    __syncthreads();
    fillW(sm, 3, tid);   // Wo; no readers of W until after next syncthreads

    // ================= attention: warp = (batch bb, head h) =================
    {
        const int bb = warp >> 2;        // 0..1
        const int h = warp & 3;          // 0..3
        const int rbase = bb * 32;
        const int c4b = h * 8;

        float4* qs4 = (float4*)(sm + QOFF);
        const float4* ks4 = (const float4*)(sm + KOFF);
        const float* vsf = (const float*)(sm + VOFF);
        float* qsf = (float*)(sm + QOFF);

        // pre-pass: q = (q + bq) * scale for this warp's 32 rows
        {
            int rq = rbase + lane;
#pragma unroll
            for (int c = 0; c < 8; ++c) {
                float4 b4 = __ldg((const float4*)bq + c4b + c);
                int ix = rq * 32 + ((c4b + c) ^ (rq & 31));
                float4 qv = qs4[ix];
                qv.x = (qv.x + b4.x) * QSCALE;
                qv.y = (qv.y + b4.y) * QSCALE;
                qv.z = (qv.z + b4.z) * QSCALE;
                qv.w = (qv.w + b4.w) * QSCALE;
                qs4[ix] = qv;
            }
        }
        __syncwarp();

        float kreg[32], vreg[32];
        {   // K row t = lane (+bias)
            int rk = rbase + lane;
#pragma unroll
            for (int c = 0; c < 8; ++c) {
                float4 b4 = __ldg((const float4*)bk + c4b + c);
                float4 kv = ks4[rk * 32 + ((c4b + c) ^ (rk & 31))];
                kreg[c * 4 + 0] = kv.x + b4.x; kreg[c * 4 + 1] = kv.y + b4.y;
                kreg[c * 4 + 2] = kv.z + b4.z; kreg[c * 4 + 3] = kv.w + b4.w;
            }
        }
        {   // V col d = lane (+bias, one scalar per thread)
            float bvd = __ldg(bv + h * 32 + lane);
            int cslot = c4b + (lane >> 2);
            int sub = lane & 3;
#pragma unroll
            for (int t = 0; t < 32; ++t) {
                int r = rbase + t;
                vreg[t] = vsf[r * 128 + ((cslot ^ (r & 31)) << 2) + sub] + bvd;
            }
        }

        const int cslot = c4b + (lane >> 2);
        const int sub = lane & 3;
#pragma unroll 1
        for (int s = 0; s < 32; ++s) {
            int rq = rbase + s;
            float sc = 0.f;
#pragma unroll
            for (int c = 0; c < 8; ++c) {
                float4 qv = qs4[rq * 32 + ((c4b + c) ^ (rq & 31))];  // broadcast
                sc = fmaf(qv.x, kreg[c * 4 + 0],
                     fmaf(qv.y, kreg[c * 4 + 1],
                     fmaf(qv.z, kreg[c * 4 + 2],
                     fmaf(qv.w, kreg[c * 4 + 3], sc))));
            }
            float m = sc;
#pragma unroll
            for (int o = 16; o; o >>= 1) m = fmaxf(m, __shfl_xor_sync(~0u, m, o));
            float p = __expf(sc - m);
            float ps = p;
#pragma unroll
            for (int o = 16; o; o >>= 1) ps += __shfl_xor_sync(~0u, ps, o);
            p /= ps;
            float ctx = 0.f;
#pragma unroll
            for (int t = 0; t < 32; ++t)
                ctx = fmaf(__shfl_sync(~0u, p, t), vreg[t], ctx);
            // write ctx (bf16 hi/lo) into A tile: row rq, col = h*32 + lane
            int cc = h * 32 + lane;
            __nv_bfloat16 hb = __float2bfloat16_rn(ctx);
            __nv_bfloat16 lb = __float2bfloat16_rn(ctx - __bfloat162float(hb));
            char* arow = sm + AOFF + rq * 512;
            int ch = cc >> 3, boff = (cc & 7) * 2, sw = rq & 7;
            *(__nv_bfloat16*)(arow + ((ch ^ sw) << 4) + boff) = hb;
            *(__nv_bfloat16*)(arow + (((16 + ch) ^ sw) << 4) + boff) = lb;
        }
    }
    __syncthreads();   // ctx + Wo complete

    // ---- out projection ----
    run_gemm(smA, smW, m0, n0, lane, acc);

    // ---- epilogue: + bo + x residual, LayerNorm, store ----
    {
        const int r1 = m0 + (lane >> 2), r2 = r1 + 8;
        const int half = warp >> 2;
        float s1a = 0.f, s2a = 0.f, s1b = 0.f, s2b = 0.f;
#pragma unroll
        for (int nt = 0; nt < 8; ++nt) {
            int c = n0 + nt * 8 + (lane & 3) * 2;
            float2 b2 = __ldg((const float2*)(bo + c));
            float2 xa = __ldg((const float2*)(inputs + tbase + (size_t)r1 * 128 + c));
            float2 xb = __ldg((const float2*)(inputs + tbase + (size_t)r2 * 128 + c));
            acc[nt][0] += b2.x + xa.x; acc[nt][1] += b2.y + xa.y;
            acc[nt][2] += b2.x + xb.x; acc[nt][3] += b2.y + xb.y;
            s1a += acc[nt][0] + acc[nt][1];
            s2a += acc[nt][0] * acc[nt][0] + acc[nt][1] * acc[nt][1];
            s1b += acc[nt][2] + acc[nt][3];
            s2b += acc[nt][2] * acc[nt][2] + acc[nt][3] * acc[nt][3];
        }
#pragma unroll
        for (int o = 1; o <= 2; o <<= 1) {
            s1a += __shfl_xor_sync(~0u, s1a, o);
            s2a += __shfl_xor_sync(~0u, s2a, o);
            s1b += __shfl_xor_sync(~0u, s1b, o);
            s2b += __shfl_xor_sync(~0u, s2b, o);
        }
        float2* part = (float2*)(sm + QOFF);
        if ((lane & 3) == 0) {
            part[r1 * 2 + half] = make_float2(s1a, s2a);
            part[r2 * 2 + half] = make_float2(s1b, s2b);
        }
        __syncthreads();
        float2 pa0 = part[r1 * 2], pa1 = part[r1 * 2 + 1];
        float2 pb0 = part[r2 * 2], pb1 = part[r2 * 2 + 1];
        float mu1 = (pa0.x + pa1.x) * (1.f / 128.f);
        float var1 = (pa0.y + pa1.y) * (1.f / 128.f) - mu1 * mu1;
        float rs1 = rsqrtf(var1 + 1e-5f);
        float mu2 = (pb0.x + pb1.x) * (1.f / 128.f);
        float var2 = (pb0.y + pb1.y) * (1.f / 128.f) - mu2 * mu2;
        float rs2 = rsqrtf(var2 + 1e-5f);
#pragma unroll
        for (int nt = 0; nt < 8; ++nt) {
            int c = n0 + nt * 8 + (lane & 3) * 2;
            float2 g2 = __ldg((const float2*)(gamma + c));
            float2 e2 = __ldg((const float2*)(beta + c));
            float2 o1, o2;
            o1.x = (acc[nt][0] - mu1) * rs1 * g2.x + e2.x;
            o1.y = (acc[nt][1] - mu1) * rs1 * g2.y + e2.y;
            o2.x = (acc[nt][2] - mu2) * rs2 * g2.x + e2.x;
            o2.y = (acc[nt][3] - mu2) * rs2 * g2.y + e2.y;
            *(float2*)(outp + tbase + (size_t)r1 * 128 + c) = o1;
            *(float2*)(outp + tbase + (size_t)r2 * 128 + c) = o2;
        }
    }
}

extern "C" void kernel_launch(void* const* d_in, const int* in_sizes, int n_in,
                              void* d_out, int out_size) {
    const float* inputs = (const float*)d_in[0];
    const float* Wq = (const float*)d_in[1];
    const float* bq = (const float*)d_in[2];
    const float* Wk = (const float*)d_in[3];
    const float* bk = (const float*)d_in[4];
    const float* Wv = (const float*)d_in[5];
    const float* bv = (const float*)d_in[6];
    const float* Wo = (const float*)d_in[7];
    const float* bo = (const float*)d_in[8];
    const float* gamma = (const float*)d_in[9];
    const float* beta  = (const float*)d_in[10];
    float* outp = (float*)d_out;

    prep_split<<<256, 256>>>(Wq, Wk, Wv, Wo);

    int grid = in_sizes[0] / 8192;   // 64 rows * 128 cols per CTA
    cudaFuncSetAttribute(fused_attn_mma,
                         cudaFuncAttributeMaxDynamicSharedMemorySize, SMEM_BYTES);
    fused_attn_mma<<<grid, NT, SMEM_BYTES>>>(inputs, bq, bk, bv, bo, gamma, beta, outp);
}

// round 7
// speedup vs baseline: 1.6962x; 1.0392x over previous
#include <cuda_runtime.h>
#include <cuda_bf16.h>
#include <cstdint>

// Fused SelfAttention via warp-level bf16 mma.sync (HMMA path; tcgen05 not
// available at the harness's sm_103 virtual target).
// E=128, S=32, H=4, D=32. CTA = 64 rows (2 batches), 256 threads, grid 8192.
// GEMMs: C = Ahi@Whi + Alo@Whi + Ahi@Wlo (bf16 split, fp32 accum), with the
// three terms FUSED into one k-loop so Whi/Ahi fragments are loaded once.
//
// SMEM bytes:
//   A   @0       : 64 rows x 512B   (bf16 [64][256]: k 0-127 = hi, 128-255 = lo)
//   W   @32768   : 128 rows x 512B  (bf16 [128][256]: Whi | Wlo), swizzled image
//   Q   @98304   : fp32 [64][128] swizzled (float4 slot ^ (row&31))
//   K   @131072  : fp32 [64][128]
//   V   @163840  : fp32 [64][128]
//   LN partials reuse Q region.

typedef unsigned int u32;

#define NT 256
#define AOFF 0
#define WOFF 32768
#define QOFF 98304
#define KOFF 131072
#define VOFF 163840
#define SMEM_BYTES 196608
#define QSCALE 0.17677669529663687f

// 4 weights x 64KB swizzled-SMEM-image of bf16 [128][256]
__device__ __align__(16) unsigned char g_Wpk[262144];

// ---------------- prep kernel: split W into bf16 hi/lo smem images ----------------
__global__ void prep_split(const float* __restrict__ Wq, const float* __restrict__ Wk,
                           const float* __restrict__ Wv, const float* __restrict__ Wo) {
    int id = blockIdx.x * blockDim.x + threadIdx.x;   // 0..65535 (u32 words)
    const float* W = (id < 16384) ? Wq : (id < 32768) ? Wk : (id < 49152) ? Wv : Wo;
    int rem = id & 16383;
    int f = rem >> 7;          // row 0..127
    int w = rem & 127;         // u32 word within 512B row
    int pc = w >> 2, j = w & 3;
    int lc = pc ^ (f & 7);     // logical 16B chunk
    int k0 = lc * 8 + j * 2;   // logical bf16 col (0..255)
    __nv_bfloat16 v[2];
#pragma unroll
    for (int i = 0; i < 2; ++i) {
        int kc = k0 + i;
        if (kc < 128) {
            v[i] = __float2bfloat16_rn(W[f * 128 + kc]);
        } else {
            float x = W[f * 128 + (kc - 128)];
            __nv_bfloat16 h = __float2bfloat16_rn(x);
            v[i] = __float2bfloat16_rn(x - __bfloat162float(h));
        }
    }
    __nv_bfloat162 p = __halves2bfloat162(v[0], v[1]);
    ((u32*)g_Wpk)[id] = *(u32*)&p;
}

// ---------------- helpers ----------------
__device__ __forceinline__ u32 s2u(const void* p) {
    u32 a;
    asm("{ .reg .u64 t; cvta.to.shared.u64 t, %1; cvt.u32.u64 %0, t; }" : "=r"(a) : "l"(p));
    return a;
}
__device__ __forceinline__ void ldsm4(u32& r0, u32& r1, u32& r2, u32& r3, u32 a) {
    asm volatile("ldmatrix.sync.aligned.m8n8.x4.shared.b16 {%0,%1,%2,%3}, [%4];"
                 : "=r"(r0), "=r"(r1), "=r"(r2), "=r"(r3) : "r"(a));
}
__device__ __forceinline__ void mma16816(float* c, u32 a0, u32 a1, u32 a2, u32 a3,
                                         u32 b0, u32 b1) {
    asm volatile(
        "mma.sync.aligned.m16n8k16.row.col.f32.bf16.bf16.f32 "
        "{%0,%1,%2,%3}, {%4,%5,%6,%7}, {%8,%9}, {%0,%1,%2,%3};"
        : "+f"(c[0]), "+f"(c[1]), "+f"(c[2]), "+f"(c[3])
        : "r"(a0), "r"(a1), "r"(a2), "r"(a3), "r"(b0), "r"(b1));
}
__device__ __forceinline__ u32 pkbf(float a, float b) {
    __nv_bfloat162 t = __halves2bfloat162(__float2bfloat16_rn(a), __float2bfloat16_rn(b));
    return *(u32*)&t;
}

// C[m0..+15][n0..+63] = A(64x128, split hi/lo) @ W^T (128x128, split hi/lo).
// Fused 3-term: per k-step load Ahi/Alo + Whi/Wlo frags once, 24 MMAs.
__device__ __forceinline__ void run_gemm(u32 smA, u32 smW, int m0, int n0, int lane,
                                         float acc[8][4]) {
    int arow = m0 + (lane & 7) + ((lane & 8) ? 8 : 0);
    u32 aRow = smA + arow * 512;
    const int asw = arow & 7;
    const int acs = lane >> 4;          // 16B column half (k lo/hi 8 within step)
    u32 bRow[4]; int bsw[4];
#pragma unroll
    for (int nt = 0; nt < 4; ++nt) {
        int brow = n0 + nt * 16 + (lane & 7) + ((lane & 16) ? 8 : 0);
        bRow[nt] = smW + brow * 512;
        bsw[nt] = brow & 7;
    }
    const int bcs = (lane >> 3) & 1;
#pragma unroll
    for (int i = 0; i < 8; ++i)
#pragma unroll
        for (int j = 0; j < 4; ++j) acc[i][j] = 0.f;

#pragma unroll
    for (int j = 0; j < 8; ++j) {
        const int ach = 2 * j + acs;
        const int bch = 2 * j + bcs;
        u32 ah0, ah1, ah2, ah3, al0, al1, al2, al3;
        ldsm4(ah0, ah1, ah2, ah3, aRow + ((ach ^ asw) << 4));
        ldsm4(al0, al1, al2, al3, aRow + (((16 + ach) ^ asw) << 4));
        u32 bh[4][4], bl[4][4];
#pragma unroll
        for (int nt = 0; nt < 4; ++nt) {
            ldsm4(bh[nt][0], bh[nt][1], bh[nt][2], bh[nt][3],
                  bRow[nt] + ((bch ^ bsw[nt]) << 4));
            ldsm4(bl[nt][0], bl[nt][1], bl[nt][2], bl[nt][3],
                  bRow[nt] + (((16 + bch) ^ bsw[nt]) << 4));
        }
#pragma unroll
        for (int nt = 0; nt < 4; ++nt) {
            mma16816(acc[2 * nt],     ah0, ah1, ah2, ah3, bh[nt][0], bh[nt][1]);
            mma16816(acc[2 * nt + 1], ah0, ah1, ah2, ah3, bh[nt][2], bh[nt][3]);
            mma16816(acc[2 * nt],     al0, al1, al2, al3, bh[nt][0], bh[nt][1]);
            mma16816(acc[2 * nt + 1], al0, al1, al2, al3, bh[nt][2], bh[nt][3]);
            mma16816(acc[2 * nt],     ah0, ah1, ah2, ah3, bl[nt][0], bl[nt][1]);
            mma16816(acc[2 * nt + 1], ah0, ah1, ah2, ah3, bl[nt][2], bl[nt][3]);
        }
    }
}

// store acc frags into fp32 swizzled [64][128] buffer
__device__ __forceinline__ void store_qkv(float* dst, const float acc[8][4],
                                          int m0, int n0, int lane) {
    const int r1 = m0 + (lane >> 2), r2 = r1 + 8;
#pragma unroll
    for (int nt = 0; nt < 8; ++nt) {
        int c = n0 + nt * 8 + (lane & 3) * 2;
        int slot = c >> 2, cr = c & 3;
        *(float2*)(dst + r1 * 128 + ((slot ^ (r1 & 31)) << 2) + cr) =
            make_float2(acc[nt][0], acc[nt][1]);
        *(float2*)(dst + r2 * 128 + ((slot ^ (r2 & 31)) << 2) + cr) =
            make_float2(acc[nt][2], acc[nt][3]);
    }
}

__device__ __forceinline__ void fillW(char* sm, int g, int tid) {
    const uint4* src = (const uint4*)g_Wpk + g * 4096;
    uint4* dst = (uint4*)(sm + WOFF);
#pragma unroll
    for (int p = 0; p < 16; ++p) dst[p * NT + tid] = __ldg(src + p * NT + tid);
}

// ---------------- main kernel ----------------
__global__ void __launch_bounds__(NT, 1)
fused_attn_mma(const float* __restrict__ inputs,
               const float* __restrict__ bq, const float* __restrict__ bk,
               const float* __restrict__ bv, const float* __restrict__ bo,
               const float* __restrict__ gamma, const float* __restrict__ beta,
               float* __restrict__ outp)
{
    extern __shared__ char sm[];
    const int tid = threadIdx.x;
    const int lane = tid & 31;
    const int warp = tid >> 5;
    const u32 smb = s2u(sm);
    const u32 smA = smb + AOFF, smW = smb + WOFF;
    const int m0 = (warp & 3) * 16;
    const int n0 = (warp >> 2) * 64;
    const size_t tbase = (size_t)blockIdx.x * 8192;

    // ---- fill A (x split hi/lo) ----
    {
        const float4* gx = (const float4*)(inputs + tbase);
#pragma unroll
        for (int p = 0; p < 8; ++p) {
            int e = p * NT + tid;
            int row = e >> 5, c4 = e & 31;
            float4 v = __ldg(gx + e);
            float hx = __bfloat162float(__float2bfloat16_rn(v.x));
            float hy = __bfloat162float(__float2bfloat16_rn(v.y));
            float hz = __bfloat162float(__float2bfloat16_rn(v.z));
            float hw = __bfloat162float(__float2bfloat16_rn(v.w));
            uint2 hi = make_uint2(pkbf(v.x, v.y), pkbf(v.z, v.w));
            uint2 lo = make_uint2(pkbf(v.x - hx, v.y - hy), pkbf(v.z - hz, v.w - hw));
            char* arow = sm + AOFF + row * 512;
            int ch = c4 >> 1, off8 = (c4 & 1) * 8, sw = row & 7;
            *(uint2*)(arow + ((ch ^ sw) << 4) + off8) = hi;
            *(uint2*)(arow + (((16 + ch) ^ sw) << 4) + off8) = lo;
        }
    }
    fillW(sm, 0, tid);
    __syncthreads();

    float acc[8][4];

    // ---- Q ----
    run_gemm(smA, smW, m0, n0, lane, acc);
    store_qkv((float*)(sm + QOFF), acc, m0, n0, lane);
    __syncthreads();
    fillW(sm, 1, tid);
    __syncthreads();
    // ---- K ----
    run_gemm(smA, smW, m0, n0, lane, acc);
    store_qkv((float*)(sm + KOFF), acc, m0, n0, lane);
    __syncthreads();
    fillW(sm, 2, tid);
    __syncthreads();
    // ---- V ----
    run_gemm(smA, smW, m0, n0, lane, acc);
    store_qkv((float*)(sm + VOFF), acc, m0, n0, lane);
    __syncthreads();
    fillW(sm, 3, tid);   // Wo; no readers of W until after next syncthreads

    // ================= attention: warp = (batch bb, head h) =================
    {
        const int bb = warp >> 2;        // 0..1
        const int h = warp & 3;          // 0..3
        const int rbase = bb * 32;
        const int c4b = h * 8;

        float4* qs4 = (float4*)(sm + QOFF);
        const float4* ks4 = (const float4*)(sm + KOFF);
        const float* vsf = (const float*)(sm + VOFF);

        // pre-pass: q = (q + bq) * scale for this warp's 32 rows
        {
            int rq = rbase + lane;
#pragma unroll
            for (int c = 0; c < 8; ++c) {
                float4 b4 = __ldg((const float4*)bq + c4b + c);
                int ix = rq * 32 + ((c4b + c) ^ (rq & 31));
                float4 qv = qs4[ix];
                qv.x = (qv.x + b4.x) * QSCALE;
                qv.y = (qv.y + b4.y) * QSCALE;
                qv.z = (qv.z + b4.z) * QSCALE;
                qv.w = (qv.w + b4.w) * QSCALE;
                qs4[ix] = qv;
            }
        }
        __syncwarp();

        float kreg[32], vreg[32];
        {   // K row t = lane (+bias)
            int rk = rbase + lane;
#pragma unroll
            for (int c = 0; c < 8; ++c) {
                float4 b4 = __ldg((const float4*)bk + c4b + c);
                float4 kv = ks4[rk * 32 + ((c4b + c) ^ (rk & 31))];
                kreg[c * 4 + 0] = kv.x + b4.x; kreg[c * 4 + 1] = kv.y + b4.y;
                kreg[c * 4 + 2] = kv.z + b4.z; kreg[c * 4 + 3] = kv.w + b4.w;
            }
        }
        {   // V col d = lane (+bias, one scalar per thread)
            float bvd = __ldg(bv + h * 32 + lane);
            int cslot = c4b + (lane >> 2);
            int sub = lane & 3;
#pragma unroll
            for (int t = 0; t < 32; ++t) {
                int r = rbase + t;
                vreg[t] = vsf[r * 128 + ((cslot ^ (r & 31)) << 2) + sub] + bvd;
            }
        }

#pragma unroll 1
        for (int s = 0; s < 32; ++s) {
            int rq = rbase + s;
            float sc = 0.f;
#pragma unroll
            for (int c = 0; c < 8; ++c) {
                float4 qv = qs4[rq * 32 + ((c4b + c) ^ (rq & 31))];  // broadcast
                sc = fmaf(qv.x, kreg[c * 4 + 0],
                     fmaf(qv.y, kreg[c * 4 + 1],
                     fmaf(qv.z, kreg[c * 4 + 2],
                     fmaf(qv.w, kreg[c * 4 + 3], sc))));
            }
            float m = sc;
#pragma unroll
            for (int o = 16; o; o >>= 1) m = fmaxf(m, __shfl_xor_sync(~0u, m, o));
            float p = __expf(sc - m);
            float ps = p;
#pragma unroll
            for (int o = 16; o; o >>= 1) ps += __shfl_xor_sync(~0u, ps, o);
            p /= ps;
            float ctx = 0.f;
#pragma unroll
            for (int t = 0; t < 32; ++t)
                ctx = fmaf(__shfl_sync(~0u, p, t), vreg[t], ctx);
            // write ctx (bf16 hi/lo) into A tile: row rq, col = h*32 + lane
            int cc = h * 32 + lane;
            __nv_bfloat16 hb = __float2bfloat16_rn(ctx);
            __nv_bfloat16 lb = __float2bfloat16_rn(ctx - __bfloat162float(hb));
            char* arow = sm + AOFF + rq * 512;
            int ch = cc >> 3, boff = (cc & 7) * 2, sw = rq & 7;
            *(__nv_bfloat16*)(arow + ((ch ^ sw) << 4) + boff) = hb;
            *(__nv_bfloat16*)(arow + (((16 + ch) ^ sw) << 4) + boff) = lb;
        }
    }
    __syncthreads();   // ctx + Wo complete

    // ---- out projection ----
    run_gemm(smA, smW, m0, n0, lane, acc);

    // ---- epilogue: + bo + x residual, LayerNorm, store ----
    {
        const int r1 = m0 + (lane >> 2), r2 = r1 + 8;
        const int half = warp >> 2;
        float s1a = 0.f, s2a = 0.f, s1b = 0.f, s2b = 0.f;
#pragma unroll
        for (int nt = 0; nt < 8; ++nt) {
            int c = n0 + nt * 8 + (lane & 3) * 2;
            float2 b2 = __ldg((const float2*)(bo + c));
            float2 xa = __ldg((const float2*)(inputs + tbase + (size_t)r1 * 128 + c));
            float2 xb = __ldg((const float2*)(inputs + tbase + (size_t)r2 * 128 + c));
            acc[nt][0] += b2.x + xa.x; acc[nt][1] += b2.y + xa.y;
            acc[nt][2] += b2.x + xb.x; acc[nt][3] += b2.y + xb.y;
            s1a += acc[nt][0] + acc[nt][1];
            s2a += acc[nt][0] * acc[nt][0] + acc[nt][1] * acc[nt][1];
            s1b += acc[nt][2] + acc[nt][3];
            s2b += acc[nt][2] * acc[nt][2] + acc[nt][3] * acc[nt][3];
        }
#pragma unroll
        for (int o = 1; o <= 2; o <<= 1) {
            s1a += __shfl_xor_sync(~0u, s1a, o);
            s2a += __shfl_xor_sync(~0u, s2a, o);
            s1b += __shfl_xor_sync(~0u, s1b, o);
            s2b += __shfl_xor_sync(~0u, s2b, o);
        }
        float2* part = (float2*)(sm + QOFF);
        if ((lane & 3) == 0) {
            part[r1 * 2 + half] = make_float2(s1a, s2a);
            part[r2 * 2 + half] = make_float2(s1b, s2b);
        }
        __syncthreads();
        float2 pa0 = part[r1 * 2], pa1 = part[r1 * 2 + 1];
        float2 pb0 = part[r2 * 2], pb1 = part[r2 * 2 + 1];
        float mu1 = (pa0.x + pa1.x) * (1.f / 128.f);
        float var1 = (pa0.y + pa1.y) * (1.f / 128.f) - mu1 * mu1;
        float rs1 = rsqrtf(var1 + 1e-5f);
        float mu2 = (pb0.x + pb1.x) * (1.f / 128.f);
        float var2 = (pb0.y + pb1.y) * (1.f / 128.f) - mu2 * mu2;
        float rs2 = rsqrtf(var2 + 1e-5f);
#pragma unroll
        for (int nt = 0; nt < 8; ++nt) {
            int c = n0 + nt * 8 + (lane & 3) * 2;
            float2 g2 = __ldg((const float2*)(gamma + c));
            float2 e2 = __ldg((const float2*)(beta + c));
            float2 o1, o2;
            o1.x = (acc[nt][0] - mu1) * rs1 * g2.x + e2.x;
            o1.y = (acc[nt][1] - mu1) * rs1 * g2.y + e2.y;
            o2.x = (acc[nt][2] - mu2) * rs2 * g2.x + e2.x;
            o2.y = (acc[nt][3] - mu2) * rs2 * g2.y + e2.y;
            *(float2*)(outp + tbase + (size_t)r1 * 128 + c) = o1;
            *(float2*)(outp + tbase + (size_t)r2 * 128 + c) = o2;
        }
    }
}

extern "C" void kernel_launch(void* const* d_in, const int* in_sizes, int n_in,
                              void* d_out, int out_size) {
    const float* inputs = (const float*)d_in[0];
    const float* Wq = (const float*)d_in[1];
    const float* bq = (const float*)d_in[2];
    const float* Wk = (const float*)d_in[3];
    const float* bk = (const float*)d_in[4];
    const float* Wv = (const float*)d_in[5];
    const float* bv = (const float*)d_in[6];
    const float* Wo = (const float*)d_in[7];
    const float* bo = (const float*)d_in[8];
    const float* gamma = (const float*)d_in[9];
    const float* beta  = (const float*)d_in[10];
    float* outp = (float*)d_out;

    prep_split<<<256, 256>>>(Wq, Wk, Wv, Wo);

    int grid = in_sizes[0] / 8192;   // 64 rows * 128 cols per CTA
    cudaFuncSetAttribute(fused_attn_mma,
                         cudaFuncAttributeMaxDynamicSharedMemorySize, SMEM_BYTES);
    fused_attn_mma<<<grid, NT, SMEM_BYTES>>>(inputs, bq, bk, bv, bo, gamma, beta, outp);
}

// round 8
// speedup vs baseline: 3.3779x; 1.9915x over previous
#include <cuda_runtime.h>
#include <cuda_bf16.h>
#include <cstdint>

// Fused SelfAttention, fully tensor-core (HMMA mma.sync bf16, 3-term split).
// E=128, S=32, H=4, D=32. CTA = 64 rows (2 batches), 256 threads, grid 8192.
// Warp w -> tile (m0=(w>>2)*32, n0=(w&3)*32) == attention block (batch, head),
// so Q stays in registers; scores and P@V are mma too. K/V stored bf16 hi/lo.
//
// SMEM:
//   A @0      : bf16 [64][256] (hi|lo), 512B rows, 16B-chunk xor swizzle. 32KB
//   W @32768  : bf16 [128][256] (hi|lo) swizzled weight image.           64KB
//   K @98304  : like A (K rows t, cols d, +bias folded).                 32KB
//   V @131072 : like A.                                                  32KB
//   LN partials @163840 : float2[64][4].                                  2KB

typedef unsigned int u32;

#define NT 256
#define AOFF 0
#define WOFF 32768
#define KOFF 98304
#define VOFF 131072
#define POFF 163840
#define SMEM_BYTES 165888
#define QSCALE 0.17677669529663687f

__device__ __align__(16) unsigned char g_Wpk[262144];

// ---------------- prep: split W into bf16 hi/lo swizzled smem images ----------
__global__ void prep_split(const float* __restrict__ Wq, const float* __restrict__ Wk,
                           const float* __restrict__ Wv, const float* __restrict__ Wo) {
    int id = blockIdx.x * blockDim.x + threadIdx.x;   // u32 words
    const float* W = (id < 16384) ? Wq : (id < 32768) ? Wk : (id < 49152) ? Wv : Wo;
    int rem = id & 16383;
    int f = rem >> 7;
    int w = rem & 127;
    int pc = w >> 2, j = w & 3;
    int lc = pc ^ (f & 7);
    int k0 = lc * 8 + j * 2;
    __nv_bfloat16 v[2];
#pragma unroll
    for (int i = 0; i < 2; ++i) {
        int kc = k0 + i;
        if (kc < 128) {
            v[i] = __float2bfloat16_rn(W[f * 128 + kc]);
        } else {
            float x = W[f * 128 + (kc - 128)];
            __nv_bfloat16 h = __float2bfloat16_rn(x);
            v[i] = __float2bfloat16_rn(x - __bfloat162float(h));
        }
    }
    __nv_bfloat162 p = __halves2bfloat162(v[0], v[1]);
    ((u32*)g_Wpk)[id] = *(u32*)&p;
}

// ---------------- helpers ----------------
__device__ __forceinline__ u32 s2u(const void* p) {
    u32 a;
    asm("{ .reg .u64 t; cvta.to.shared.u64 t, %1; cvt.u32.u64 %0, t; }" : "=r"(a) : "l"(p));
    return a;
}
__device__ __forceinline__ void ldsm4(u32* r, u32 a) {
    asm volatile("ldmatrix.sync.aligned.m8n8.x4.shared.b16 {%0,%1,%2,%3}, [%4];"
                 : "=r"(r[0]), "=r"(r[1]), "=r"(r[2]), "=r"(r[3]) : "r"(a));
}
__device__ __forceinline__ void ldsm4t(u32* r, u32 a) {
    asm volatile("ldmatrix.sync.aligned.m8n8.x4.trans.shared.b16 {%0,%1,%2,%3}, [%4];"
                 : "=r"(r[0]), "=r"(r[1]), "=r"(r[2]), "=r"(r[3]) : "r"(a));
}
__device__ __forceinline__ void mma16816(float* c, const u32* a, u32 b0, u32 b1) {
    asm volatile(
        "mma.sync.aligned.m16n8k16.row.col.f32.bf16.bf16.f32 "
        "{%0,%1,%2,%3}, {%4,%5,%6,%7}, {%8,%9}, {%0,%1,%2,%3};"
        : "+f"(c[0]), "+f"(c[1]), "+f"(c[2]), "+f"(c[3])
        : "r"(a[0]), "r"(a[1]), "r"(a[2]), "r"(a[3]), "r"(b0), "r"(b1));
}
__device__ __forceinline__ u32 pkbf(float a, float b) {
    __nv_bfloat162 t = __halves2bfloat162(__float2bfloat16_rn(a), __float2bfloat16_rn(b));
    return *(u32*)&t;
}
__device__ __forceinline__ u32 pkbf_lo(float a, float b, u32 hi) {
    __nv_bfloat162 h = *(__nv_bfloat162*)&hi;
    return pkbf(a - __bfloat162float(h.x), b - __bfloat162float(h.y));
}

// C[m0:+32][n0:+32] = A(64x128 hi/lo) @ W^T(128x128 hi/lo), 3-term split.
__device__ __forceinline__ void gemm32(u32 smA, u32 smW, int m0, int n0, int lane,
                                       float acc[2][4][4]) {
    u32 aRow[2]; int asw[2];
#pragma unroll
    for (int mt = 0; mt < 2; ++mt) {
        int ar = m0 + mt * 16 + (lane & 7) + ((lane & 8) ? 8 : 0);
        aRow[mt] = smA + ar * 512; asw[mt] = ar & 7;
    }
    const int acs = lane >> 4;
    u32 bRow[2]; int bsw[2];
#pragma unroll
    for (int ng = 0; ng < 2; ++ng) {
        int br = n0 + ng * 16 + (lane & 7) + ((lane & 16) ? 8 : 0);
        bRow[ng] = smW + br * 512; bsw[ng] = br & 7;
    }
    const int bcs = (lane >> 3) & 1;
#pragma unroll
    for (int mt = 0; mt < 2; ++mt)
#pragma unroll
        for (int nf = 0; nf < 4; ++nf)
#pragma unroll
            for (int c = 0; c < 4; ++c) acc[mt][nf][c] = 0.f;

#pragma unroll
    for (int j = 0; j < 8; ++j) {
        const int ach = 2 * j + acs, bch = 2 * j + bcs;
        u32 ah[2][4], al[2][4], bh[2][4], bl[2][4];
#pragma unroll
        for (int mt = 0; mt < 2; ++mt) {
            ldsm4(ah[mt], aRow[mt] + ((ach ^ asw[mt]) << 4));
            ldsm4(al[mt], aRow[mt] + (((16 + ach) ^ asw[mt]) << 4));
        }
#pragma unroll
        for (int ng = 0; ng < 2; ++ng) {
            ldsm4(bh[ng], bRow[ng] + ((bch ^ bsw[ng]) << 4));
            ldsm4(bl[ng], bRow[ng] + (((16 + bch) ^ bsw[ng]) << 4));
        }
#pragma unroll
        for (int mt = 0; mt < 2; ++mt)
#pragma unroll
            for (int ng = 0; ng < 2; ++ng) {
                mma16816(acc[mt][2 * ng],     ah[mt], bh[ng][0], bh[ng][1]);
                mma16816(acc[mt][2 * ng + 1], ah[mt], bh[ng][2], bh[ng][3]);
                mma16816(acc[mt][2 * ng],     al[mt], bh[ng][0], bh[ng][1]);
                mma16816(acc[mt][2 * ng + 1], al[mt], bh[ng][2], bh[ng][3]);
                mma16816(acc[mt][2 * ng],     ah[mt], bl[ng][0], bl[ng][1]);
                mma16816(acc[mt][2 * ng + 1], ah[mt], bl[ng][2], bl[ng][3]);
            }
    }
}

// c-frags (+optional bias) -> bf16 hi/lo into an A-style [64][256] image.
__device__ __forceinline__ void store_split(char* dst, const float acc[2][4][4],
                                            int m0, int n0, int lane,
                                            const float* bias) {
#pragma unroll
    for (int mt = 0; mt < 2; ++mt) {
        int r = m0 + mt * 16 + (lane >> 2);
        char* row0 = dst + r * 512;
        char* row1 = dst + (r + 8) * 512;
        int sw = r & 7;   // (r+8)&7 == r&7
#pragma unroll
        for (int nf = 0; nf < 4; ++nf) {
            int c = n0 + nf * 8 + 2 * (lane & 3);
            float v0 = acc[mt][nf][0], v1 = acc[mt][nf][1];
            float v2 = acc[mt][nf][2], v3 = acc[mt][nf][3];
            if (bias) {
                float2 b2 = __ldg((const float2*)(bias + c));
                v0 += b2.x; v1 += b2.y; v2 += b2.x; v3 += b2.y;
            }
            u32 h01 = pkbf(v0, v1), l01 = pkbf_lo(v0, v1, h01);
            u32 h23 = pkbf(v2, v3), l23 = pkbf_lo(v2, v3, h23);
            int ch = c >> 3, bo_ = (c & 7) * 2;
            *(u32*)(row0 + ((ch ^ sw) << 4) + bo_) = h01;
            *(u32*)(row0 + (((16 + ch) ^ sw) << 4) + bo_) = l01;
            *(u32*)(row1 + ((ch ^ sw) << 4) + bo_) = h23;
            *(u32*)(row1 + (((16 + ch) ^ sw) << 4) + bo_) = l23;
        }
    }
}

__device__ __forceinline__ void fillW(char* sm, int g, int tid) {
    const uint4* src = (const uint4*)g_Wpk + g * 4096;
    uint4* dst = (uint4*)(sm + WOFF);
#pragma unroll
    for (int p = 0; p < 16; ++p) dst[p * NT + tid] = __ldg(src + p * NT + tid);
}

// ---------------- main kernel ----------------
__global__ void __launch_bounds__(NT, 1)
fused_attn_fa(const float* __restrict__ inputs,
              const float* __restrict__ bq, const float* __restrict__ bk,
              const float* __restrict__ bv, const float* __restrict__ bo,
              const float* __restrict__ gamma, const float* __restrict__ beta,
              float* __restrict__ outp)
{
    extern __shared__ char sm[];
    const int tid = threadIdx.x;
    const int lane = tid & 31;
    const int warp = tid >> 5;
    const u32 smb = s2u(sm);
    const u32 smA = smb + AOFF, smW = smb + WOFF;
    const u32 smK = smb + KOFF, smV = smb + VOFF;
    const int m0 = (warp >> 2) * 32;    // batch block (rows)
    const int n0 = (warp & 3) * 32;     // head block (cols)
    const int h = warp & 3;
    const size_t tbase = (size_t)blockIdx.x * 8192;

    // ---- fill A (x split hi/lo) ----
    {
        const float4* gx = (const float4*)(inputs + tbase);
#pragma unroll
        for (int p = 0; p < 8; ++p) {
            int e = p * NT + tid;
            int row = e >> 5, c4 = e & 31;
            float4 v = __ldg(gx + e);
            float hx = __bfloat162float(__float2bfloat16_rn(v.x));
            float hy = __bfloat162float(__float2bfloat16_rn(v.y));
            float hz = __bfloat162float(__float2bfloat16_rn(v.z));
            float hw = __bfloat162float(__float2bfloat16_rn(v.w));
            uint2 hi = make_uint2(pkbf(v.x, v.y), pkbf(v.z, v.w));
            uint2 lo = make_uint2(pkbf(v.x - hx, v.y - hy), pkbf(v.z - hz, v.w - hw));
            char* arow = sm + AOFF + row * 512;
            int ch = c4 >> 1, off8 = (c4 & 1) * 8, sw = row & 7;
            *(uint2*)(arow + ((ch ^ sw) << 4) + off8) = hi;
            *(uint2*)(arow + (((16 + ch) ^ sw) << 4) + off8) = lo;
        }
    }
    fillW(sm, 0, tid);
    __syncthreads();

    float acc[2][4][4];

    // ---- Q gemm; keep as bf16 a-frags in registers (bias+scale folded) ----
    gemm32(smA, smW, m0, n0, lane, acc);
    u32 qh[2][2][4], ql[2][2][4];
#pragma unroll
    for (int mt = 0; mt < 2; ++mt)
#pragma unroll
        for (int nf = 0; nf < 4; ++nf) {
            int c = n0 + nf * 8 + 2 * (lane & 3);
            float2 b2 = __ldg((const float2*)(bq + c));
            float q0 = (acc[mt][nf][0] + b2.x) * QSCALE;
            float q1 = (acc[mt][nf][1] + b2.y) * QSCALE;
            float q2 = (acc[mt][nf][2] + b2.x) * QSCALE;
            float q3 = (acc[mt][nf][3] + b2.y) * QSCALE;
            int ks = nf >> 1, o = (nf & 1) * 2;
            qh[mt][ks][o] = pkbf(q0, q1);
            qh[mt][ks][o + 1] = pkbf(q2, q3);
            ql[mt][ks][o] = pkbf_lo(q0, q1, qh[mt][ks][o]);
            ql[mt][ks][o + 1] = pkbf_lo(q2, q3, qh[mt][ks][o + 1]);
        }
    __syncthreads();
    fillW(sm, 1, tid);
    __syncthreads();

    // ---- K gemm -> K smem (bf16 hi/lo, +bk) ----
    gemm32(smA, smW, m0, n0, lane, acc);
    store_split(sm + KOFF, acc, m0, n0, lane, bk);
    __syncthreads();
    fillW(sm, 2, tid);
    __syncthreads();

    // ---- V gemm -> V smem (bf16 hi/lo, +bv) ----
    gemm32(smA, smW, m0, n0, lane, acc);
    store_split(sm + VOFF, acc, m0, n0, lane, bv);
    __syncthreads();
    fillW(sm, 3, tid);   // Wo fill overlaps attention (disjoint smem)

    // ================= attention (all-mma) =================
    float S[2][4][4];
#pragma unroll
    for (int mt = 0; mt < 2; ++mt)
#pragma unroll
        for (int nf = 0; nf < 4; ++nf)
#pragma unroll
            for (int c = 0; c < 4; ++c) S[mt][nf][c] = 0.f;

    // scores: S = Q @ K^T ; B-frags from K rows (n = t), k-chunks = head d cols
    {
        u32 bRow[2]; int bsw[2];
#pragma unroll
        for (int ng = 0; ng < 2; ++ng) {
            int br = m0 + ng * 16 + (lane & 7) + ((lane & 16) ? 8 : 0);
            bRow[ng] = smK + br * 512; bsw[ng] = br & 7;
        }
        const int bcs = (lane >> 3) & 1;
#pragma unroll
        for (int ks = 0; ks < 2; ++ks) {
            int bch = h * 4 + 2 * ks + bcs;
            u32 kh[2][4], kl[2][4];
#pragma unroll
            for (int ng = 0; ng < 2; ++ng) {
                ldsm4(kh[ng], bRow[ng] + ((bch ^ bsw[ng]) << 4));
                ldsm4(kl[ng], bRow[ng] + (((16 + bch) ^ bsw[ng]) << 4));
            }
#pragma unroll
            for (int mt = 0; mt < 2; ++mt)
#pragma unroll
                for (int ng = 0; ng < 2; ++ng) {
                    mma16816(S[mt][2 * ng],     qh[mt][ks], kh[ng][0], kh[ng][1]);
                    mma16816(S[mt][2 * ng + 1], qh[mt][ks], kh[ng][2], kh[ng][3]);
                    mma16816(S[mt][2 * ng],     ql[mt][ks], kh[ng][0], kh[ng][1]);
                    mma16816(S[mt][2 * ng + 1], ql[mt][ks], kh[ng][2], kh[ng][3]);
                    mma16816(S[mt][2 * ng],     qh[mt][ks], kl[ng][0], kl[ng][1]);
                    mma16816(S[mt][2 * ng + 1], qh[mt][ks], kl[ng][2], kl[ng][3]);
                }
        }
    }

    // softmax over t (row groups of 4 lanes)
    u32 ph[2][2][4], pl[2][2][4];
    {
        float mx[2][2], iv[2][2];
#pragma unroll
        for (int mt = 0; mt < 2; ++mt)
#pragma unroll
            for (int hf = 0; hf < 2; ++hf) {
                float m = -1e30f;
#pragma unroll
                for (int nf = 0; nf < 4; ++nf)
                    m = fmaxf(m, fmaxf(S[mt][nf][hf * 2], S[mt][nf][hf * 2 + 1]));
                m = fmaxf(m, __shfl_xor_sync(~0u, m, 1));
                m = fmaxf(m, __shfl_xor_sync(~0u, m, 2));
                mx[mt][hf] = m;
            }
#pragma unroll
        for (int mt = 0; mt < 2; ++mt)
#pragma unroll
            for (int nf = 0; nf < 4; ++nf) {
                S[mt][nf][0] = __expf(S[mt][nf][0] - mx[mt][0]);
                S[mt][nf][1] = __expf(S[mt][nf][1] - mx[mt][0]);
                S[mt][nf][2] = __expf(S[mt][nf][2] - mx[mt][1]);
                S[mt][nf][3] = __expf(S[mt][nf][3] - mx[mt][1]);
            }
#pragma unroll
        for (int mt = 0; mt < 2; ++mt)
#pragma unroll
            for (int hf = 0; hf < 2; ++hf) {
                float s = 0.f;
#pragma unroll
                for (int nf = 0; nf < 4; ++nf)
                    s += S[mt][nf][hf * 2] + S[mt][nf][hf * 2 + 1];
                s += __shfl_xor_sync(~0u, s, 1);
                s += __shfl_xor_sync(~0u, s, 2);
                iv[mt][hf] = 1.f / s;
            }
#pragma unroll
        for (int mt = 0; mt < 2; ++mt)
#pragma unroll
            for (int nf = 0; nf < 4; ++nf) {
                float p0 = S[mt][nf][0] * iv[mt][0];
                float p1 = S[mt][nf][1] * iv[mt][0];
                float p2 = S[mt][nf][2] * iv[mt][1];
                float p3 = S[mt][nf][3] * iv[mt][1];
                int ks = nf >> 1, o = (nf & 1) * 2;
                ph[mt][ks][o] = pkbf(p0, p1);
                ph[mt][ks][o + 1] = pkbf(p2, p3);
                pl[mt][ks][o] = pkbf_lo(p0, p1, ph[mt][ks][o]);
                pl[mt][ks][o + 1] = pkbf_lo(p2, p3, ph[mt][ks][o + 1]);
            }
    }

    // ctx = P @ V ; V B-frags via ldmatrix.trans on V rows (k = t)
    float C[2][4][4];
#pragma unroll
    for (int mt = 0; mt < 2; ++mt)
#pragma unroll
        for (int nf = 0; nf < 4; ++nf)
#pragma unroll
            for (int c = 0; c < 4; ++c) C[mt][nf][c] = 0.f;
    {
#pragma unroll
        for (int ks = 0; ks < 2; ++ks) {
            int trow = m0 + ks * 16 + ((lane >> 3) & 1) * 8 + (lane & 7);
            u32 vrow = smV + trow * 512;
            int tsw = trow & 7;
#pragma unroll
            for (int p = 0; p < 2; ++p) {
                int ch = h * 4 + 2 * p + (lane >> 4);
                u32 vh[4], vl[4];
                ldsm4t(vh, vrow + ((ch ^ tsw) << 4));
                ldsm4t(vl, vrow + (((16 + ch) ^ tsw) << 4));
#pragma unroll
                for (int mt = 0; mt < 2; ++mt) {
                    mma16816(C[mt][2 * p],     ph[mt][ks], vh[0], vh[1]);
                    mma16816(C[mt][2 * p + 1], ph[mt][ks], vh[2], vh[3]);
                    mma16816(C[mt][2 * p],     pl[mt][ks], vh[0], vh[1]);
                    mma16816(C[mt][2 * p + 1], pl[mt][ks], vh[2], vh[3]);
                    mma16816(C[mt][2 * p],     ph[mt][ks], vl[0], vl[1]);
                    mma16816(C[mt][2 * p + 1], ph[mt][ks], vl[2], vl[3]);
                }
            }
        }
    }

    // ctx -> A tile (bf16 hi/lo) at rows m0.., cols h*32..
    store_split(sm + AOFF, C, m0, n0, lane, nullptr);
    __syncthreads();

    // ---- out projection ----
    gemm32(smA, smW, m0, n0, lane, acc);

    // ---- epilogue: + bo + x residual, LayerNorm (cross-warp partials), store ----
    {
        float s1[2][2] = {{0.f, 0.f}, {0.f, 0.f}};
        float s2[2][2] = {{0.f, 0.f}, {0.f, 0.f}};
#pragma unroll
        for (int mt = 0; mt < 2; ++mt) {
            int r = m0 + mt * 16 + (lane >> 2);
#pragma unroll
            for (int nf = 0; nf < 4; ++nf) {
                int c = n0 + nf * 8 + 2 * (lane & 3);
                float2 b2 = __ldg((const float2*)(bo + c));
                float2 xa = __ldg((const float2*)(inputs + tbase + (size_t)r * 128 + c));
                float2 xb = __ldg((const float2*)(inputs + tbase + (size_t)(r + 8) * 128 + c));
                acc[mt][nf][0] += b2.x + xa.x; acc[mt][nf][1] += b2.y + xa.y;
                acc[mt][nf][2] += b2.x + xb.x; acc[mt][nf][3] += b2.y + xb.y;
                s1[mt][0] += acc[mt][nf][0] + acc[mt][nf][1];
                s2[mt][0] += acc[mt][nf][0] * acc[mt][nf][0] + acc[mt][nf][1] * acc[mt][nf][1];
                s1[mt][1] += acc[mt][nf][2] + acc[mt][nf][3];
                s2[mt][1] += acc[mt][nf][2] * acc[mt][nf][2] + acc[mt][nf][3] * acc[mt][nf][3];
            }
        }
#pragma unroll
        for (int mt = 0; mt < 2; ++mt)
#pragma unroll
            for (int hf = 0; hf < 2; ++hf) {
                s1[mt][hf] += __shfl_xor_sync(~0u, s1[mt][hf], 1);
                s1[mt][hf] += __shfl_xor_sync(~0u, s1[mt][hf], 2);
                s2[mt][hf] += __shfl_xor_sync(~0u, s2[mt][hf], 1);
                s2[mt][hf] += __shfl_xor_sync(~0u, s2[mt][hf], 2);
            }
        float2* part = (float2*)(sm + POFF);
        if ((lane & 3) == 0) {
#pragma unroll
            for (int mt = 0; mt < 2; ++mt) {
                int r = m0 + mt * 16 + (lane >> 2);
                part[r * 4 + h] = make_float2(s1[mt][0], s2[mt][0]);
                part[(r + 8) * 4 + h] = make_float2(s1[mt][1], s2[mt][1]);
            }
        }
        __syncthreads();
        float mu[2][2], rs[2][2];
#pragma unroll
        for (int mt = 0; mt < 2; ++mt)
#pragma unroll
            for (int hf = 0; hf < 2; ++hf) {
                int r = m0 + mt * 16 + (lane >> 2) + hf * 8;
                float2 p0 = part[r * 4 + 0], p1 = part[r * 4 + 1];
                float2 p2 = part[r * 4 + 2], p3 = part[r * 4 + 3];
                float S1 = p0.x + p1.x + p2.x + p3.x;
                float S2 = p0.y + p1.y + p2.y + p3.y;
                float m = S1 * (1.f / 128.f);
                float v = S2 * (1.f / 128.f) - m * m;
                mu[mt][hf] = m;
                rs[mt][hf] = rsqrtf(v + 1e-5f);
            }
#pragma unroll
        for (int mt = 0; mt < 2; ++mt) {
            int r = m0 + mt * 16 + (lane >> 2);
#pragma unroll
            for (int nf = 0; nf < 4; ++nf) {
                int c = n0 + nf * 8 + 2 * (lane & 3);
                float2 g2 = __ldg((const float2*)(gamma + c));
                float2 e2 = __ldg((const float2*)(beta + c));
                float2 o1, o2;
                o1.x = (acc[mt][nf][0] - mu[mt][0]) * rs[mt][0] * g2.x + e2.x;
                o1.y = (acc[mt][nf][1] - mu[mt][0]) * rs[mt][0] * g2.y + e2.y;
                o2.x = (acc[mt][nf][2] - mu[mt][1]) * rs[mt][1] * g2.x + e2.x;
                o2.y = (acc[mt][nf][3] - mu[mt][1]) * rs[mt][1] * g2.y + e2.y;
                *(float2*)(outp + tbase + (size_t)r * 128 + c) = o1;
                *(float2*)(outp + tbase + (size_t)(r + 8) * 128 + c) = o2;
            }
        }
    }
}

extern "C" void kernel_launch(void* const* d_in, const int* in_sizes, int n_in,
                              void* d_out, int out_size) {
    const float* inputs = (const float*)d_in[0];
    const float* Wq = (const float*)d_in[1];
    const float* bq = (const float*)d_in[2];
    const float* Wk = (const float*)d_in[3];
    const float* bk = (const float*)d_in[4];
    const float* Wv = (const float*)d_in[5];
    const float* bv = (const float*)d_in[6];
    const float* Wo = (const float*)d_in[7];
    const float* bo = (const float*)d_in[8];
    const float* gamma = (const float*)d_in[9];
    const float* beta  = (const float*)d_in[10];
    float* outp = (float*)d_out;

    prep_split<<<256, 256>>>(Wq, Wk, Wv, Wo);

    int grid = in_sizes[0] / 8192;
    cudaFuncSetAttribute(fused_attn_fa,
                         cudaFuncAttributeMaxDynamicSharedMemorySize, SMEM_BYTES);
    fused_attn_fa<<<grid, NT, SMEM_BYTES>>>(inputs, bq, bk, bv, bo, gamma, beta, outp);
}

// round 9
// speedup vs baseline: 3.3789x; 1.0003x over previous
#include <cuda_runtime.h>
#include <cuda_bf16.h>
#include <cstdint>

// Fused SelfAttention, fully tensor-core (HMMA mma.sync bf16, 3-term split).
// E=128, S=32, H=4, D=32. CTA = 64 rows (2 batches), 256 threads, grid 8192.
// Warp w -> tile (m0=(w>>2)*32, n0=(w&3)*32) == attention block (batch, head),
// so Q stays in registers; scores and P@V are mma too. K/V stored bf16 hi/lo.
// R8: MMA issue reordered into 3 passes over 8 independent accumulators
// (hh -> lh -> hl) to break RAW chains; bitwise-identical accumulation order
// per accumulator vs R7.
//
// SMEM:
//   A @0      : bf16 [64][256] (hi|lo), 512B rows, 16B-chunk xor swizzle. 32KB
//   W @32768  : bf16 [128][256] (hi|lo) swizzled weight image.           64KB
//   K @98304  : like A (K rows t, cols d, +bias folded).                 32KB
//   V @131072 : like A.                                                  32KB
//   LN partials @163840 : float2[64][4].                                  2KB

typedef unsigned int u32;

#define NT 256
#define AOFF 0
#define WOFF 32768
#define KOFF 98304
#define VOFF 131072
#define POFF 163840
#define SMEM_BYTES 165888
#define QSCALE 0.17677669529663687f

__device__ __align__(16) unsigned char g_Wpk[262144];

// ---------------- prep: split W into bf16 hi/lo swizzled smem images ----------
__global__ void prep_split(const float* __restrict__ Wq, const float* __restrict__ Wk,
                           const float* __restrict__ Wv, const float* __restrict__ Wo) {
    int id = blockIdx.x * blockDim.x + threadIdx.x;   // u32 words
    const float* W = (id < 16384) ? Wq : (id < 32768) ? Wk : (id < 49152) ? Wv : Wo;
    int rem = id & 16383;
    int f = rem >> 7;
    int w = rem & 127;
    int pc = w >> 2, j = w & 3;
    int lc = pc ^ (f & 7);
    int k0 = lc * 8 + j * 2;
    __nv_bfloat16 v[2];
#pragma unroll
    for (int i = 0; i < 2; ++i) {
        int kc = k0 + i;
        if (kc < 128) {
            v[i] = __float2bfloat16_rn(W[f * 128 + kc]);
        } else {
            float x = W[f * 128 + (kc - 128)];
            __nv_bfloat16 h = __float2bfloat16_rn(x);
            v[i] = __float2bfloat16_rn(x - __bfloat162float(h));
        }
    }
    __nv_bfloat162 p = __halves2bfloat162(v[0], v[1]);
    ((u32*)g_Wpk)[id] = *(u32*)&p;
}

// ---------------- helpers ----------------
__device__ __forceinline__ u32 s2u(const void* p) {
    u32 a;
    asm("{ .reg .u64 t; cvta.to.shared.u64 t, %1; cvt.u32.u64 %0, t; }" : "=r"(a) : "l"(p));
    return a;
}
__device__ __forceinline__ void ldsm4(u32* r, u32 a) {
    asm volatile("ldmatrix.sync.aligned.m8n8.x4.shared.b16 {%0,%1,%2,%3}, [%4];"
                 : "=r"(r[0]), "=r"(r[1]), "=r"(r[2]), "=r"(r[3]) : "r"(a));
}
__device__ __forceinline__ void ldsm4t(u32* r, u32 a) {
    asm volatile("ldmatrix.sync.aligned.m8n8.x4.trans.shared.b16 {%0,%1,%2,%3}, [%4];"
                 : "=r"(r[0]), "=r"(r[1]), "=r"(r[2]), "=r"(r[3]) : "r"(a));
}
__device__ __forceinline__ void mma16816(float* c, const u32* a, u32 b0, u32 b1) {
    asm volatile(
        "mma.sync.aligned.m16n8k16.row.col.f32.bf16.bf16.f32 "
        "{%0,%1,%2,%3}, {%4,%5,%6,%7}, {%8,%9}, {%0,%1,%2,%3};"
        : "+f"(c[0]), "+f"(c[1]), "+f"(c[2]), "+f"(c[3])
        : "r"(a[0]), "r"(a[1]), "r"(a[2]), "r"(a[3]), "r"(b0), "r"(b1));
}
__device__ __forceinline__ u32 pkbf(float a, float b) {
    __nv_bfloat162 t = __halves2bfloat162(__float2bfloat16_rn(a), __float2bfloat16_rn(b));
    return *(u32*)&t;
}
__device__ __forceinline__ u32 pkbf_lo(float a, float b, u32 hi) {
    __nv_bfloat162 h = *(__nv_bfloat162*)&hi;
    return pkbf(a - __bfloat162float(h.x), b - __bfloat162float(h.y));
}

// C[m0:+32][n0:+32] = A(64x128 hi/lo) @ W^T(128x128 hi/lo), 3-term split.
// MMAs issued as 3 passes of 8 independent accumulators per k-step.
__device__ __forceinline__ void gemm32(u32 smA, u32 smW, int m0, int n0, int lane,
                                       float acc[2][4][4]) {
    u32 aRow[2]; int asw[2];
#pragma unroll
    for (int mt = 0; mt < 2; ++mt) {
        int ar = m0 + mt * 16 + (lane & 7) + ((lane & 8) ? 8 : 0);
        aRow[mt] = smA + ar * 512; asw[mt] = ar & 7;
    }
    const int acs = lane >> 4;
    u32 bRow[2]; int bsw[2];
#pragma unroll
    for (int ng = 0; ng < 2; ++ng) {
        int br = n0 + ng * 16 + (lane & 7) + ((lane & 16) ? 8 : 0);
        bRow[ng] = smW + br * 512; bsw[ng] = br & 7;
    }
    const int bcs = (lane >> 3) & 1;
#pragma unroll
    for (int mt = 0; mt < 2; ++mt)
#pragma unroll
        for (int nf = 0; nf < 4; ++nf)
#pragma unroll
            for (int c = 0; c < 4; ++c) acc[mt][nf][c] = 0.f;

#pragma unroll
    for (int j = 0; j < 8; ++j) {
        const int ach = 2 * j + acs, bch = 2 * j + bcs;
        u32 ah[2][4], al[2][4], bh[2][4], bl[2][4];
#pragma unroll
        for (int mt = 0; mt < 2; ++mt) {
            ldsm4(ah[mt], aRow[mt] + ((ach ^ asw[mt]) << 4));
            ldsm4(al[mt], aRow[mt] + (((16 + ach) ^ asw[mt]) << 4));
        }
#pragma unroll
        for (int ng = 0; ng < 2; ++ng) {
            ldsm4(bh[ng], bRow[ng] + ((bch ^ bsw[ng]) << 4));
            ldsm4(bl[ng], bRow[ng] + (((16 + bch) ^ bsw[ng]) << 4));
        }
        // pass 1: Ahi @ Whi  (8 independent MMAs)
#pragma unroll
        for (int mt = 0; mt < 2; ++mt)
#pragma unroll
            for (int ng = 0; ng < 2; ++ng) {
                mma16816(acc[mt][2 * ng],     ah[mt], bh[ng][0], bh[ng][1]);
                mma16816(acc[mt][2 * ng + 1], ah[mt], bh[ng][2], bh[ng][3]);
            }
        // pass 2: Alo @ Whi
#pragma unroll
        for (int mt = 0; mt < 2; ++mt)
#pragma unroll
            for (int ng = 0; ng < 2; ++ng) {
                mma16816(acc[mt][2 * ng],     al[mt], bh[ng][0], bh[ng][1]);
                mma16816(acc[mt][2 * ng + 1], al[mt], bh[ng][2], bh[ng][3]);
            }
        // pass 3: Ahi @ Wlo
#pragma unroll
        for (int mt = 0; mt < 2; ++mt)
#pragma unroll
            for (int ng = 0; ng < 2; ++ng) {
                mma16816(acc[mt][2 * ng],     ah[mt], bl[ng][0], bl[ng][1]);
                mma16816(acc[mt][2 * ng + 1], ah[mt], bl[ng][2], bl[ng][3]);
            }
    }
}

// c-frags (+optional bias) -> bf16 hi/lo into an A-style [64][256] image.
__device__ __forceinline__ void store_split(char* dst, const float acc[2][4][4],
                                            int m0, int n0, int lane,
                                            const float* bias) {
#pragma unroll
    for (int mt = 0; mt < 2; ++mt) {
        int r = m0 + mt * 16 + (lane >> 2);
        char* row0 = dst + r * 512;
        char* row1 = dst + (r + 8) * 512;
        int sw = r & 7;   // (r+8)&7 == r&7
#pragma unroll
        for (int nf = 0; nf < 4; ++nf) {
            int c = n0 + nf * 8 + 2 * (lane & 3);
            float v0 = acc[mt][nf][0], v1 = acc[mt][nf][1];
            float v2 = acc[mt][nf][2], v3 = acc[mt][nf][3];
            if (bias) {
                float2 b2 = __ldg((const float2*)(bias + c));
                v0 += b2.x; v1 += b2.y; v2 += b2.x; v3 += b2.y;
            }
            u32 h01 = pkbf(v0, v1), l01 = pkbf_lo(v0, v1, h01);
            u32 h23 = pkbf(v2, v3), l23 = pkbf_lo(v2, v3, h23);
            int ch = c >> 3, bo_ = (c & 7) * 2;
            *(u32*)(row0 + ((ch ^ sw) << 4) + bo_) = h01;
            *(u32*)(row0 + (((16 + ch) ^ sw) << 4) + bo_) = l01;
            *(u32*)(row1 + ((ch ^ sw) << 4) + bo_) = h23;
            *(u32*)(row1 + (((16 + ch) ^ sw) << 4) + bo_) = l23;
        }
    }
}

__device__ __forceinline__ void fillW(char* sm, int g, int tid) {
    const uint4* src = (const uint4*)g_Wpk + g * 4096;
    uint4* dst = (uint4*)(sm + WOFF);
#pragma unroll
    for (int p = 0; p < 16; ++p) dst[p * NT + tid] = __ldg(src + p * NT + tid);
}

// ---------------- main kernel ----------------
__global__ void __launch_bounds__(NT, 1)
fused_attn_fa(const float* __restrict__ inputs,
              const float* __restrict__ bq, const float* __restrict__ bk,
              const float* __restrict__ bv, const float* __restrict__ bo,
              const float* __restrict__ gamma, const float* __restrict__ beta,
              float* __restrict__ outp)
{
    extern __shared__ char sm[];
    const int tid = threadIdx.x;
    const int lane = tid & 31;
    const int warp = tid >> 5;
    const u32 smb = s2u(sm);
    const u32 smA = smb + AOFF, smW = smb + WOFF;
    const u32 smK = smb + KOFF, smV = smb + VOFF;
    const int m0 = (warp >> 2) * 32;    // batch block (rows)
    const int n0 = (warp & 3) * 32;     // head block (cols)
    const int h = warp & 3;
    const size_t tbase = (size_t)blockIdx.x * 8192;

    // ---- fill A (x split hi/lo) ----
    {
        const float4* gx = (const float4*)(inputs + tbase);
#pragma unroll
        for (int p = 0; p < 8; ++p) {
            int e = p * NT + tid;
            int row = e >> 5, c4 = e & 31;
            float4 v = __ldg(gx + e);
            float hx = __bfloat162float(__float2bfloat16_rn(v.x));
            float hy = __bfloat162float(__float2bfloat16_rn(v.y));
            float hz = __bfloat162float(__float2bfloat16_rn(v.z));
            float hw = __bfloat162float(__float2bfloat16_rn(v.w));
            uint2 hi = make_uint2(pkbf(v.x, v.y), pkbf(v.z, v.w));
            uint2 lo = make_uint2(pkbf(v.x - hx, v.y - hy), pkbf(v.z - hz, v.w - hw));
            char* arow = sm + AOFF + row * 512;
            int ch = c4 >> 1, off8 = (c4 & 1) * 8, sw = row & 7;
            *(uint2*)(arow + ((ch ^ sw) << 4) + off8) = hi;
            *(uint2*)(arow + (((16 + ch) ^ sw) << 4) + off8) = lo;
        }
    }
    fillW(sm, 0, tid);
    __syncthreads();

    float acc[2][4][4];

    // ---- Q gemm; keep as bf16 a-frags in registers (bias+scale folded) ----
    gemm32(smA, smW, m0, n0, lane, acc);
    u32 qh[2][2][4], ql[2][2][4];
#pragma unroll
    for (int mt = 0; mt < 2; ++mt)
#pragma unroll
        for (int nf = 0; nf < 4; ++nf) {
            int c = n0 + nf * 8 + 2 * (lane & 3);
            float2 b2 = __ldg((const float2*)(bq + c));
            float q0 = (acc[mt][nf][0] + b2.x) * QSCALE;
            float q1 = (acc[mt][nf][1] + b2.y) * QSCALE;
            float q2 = (acc[mt][nf][2] + b2.x) * QSCALE;
            float q3 = (acc[mt][nf][3] + b2.y) * QSCALE;
            int ks = nf >> 1, o = (nf & 1) * 2;
            qh[mt][ks][o] = pkbf(q0, q1);
            qh[mt][ks][o + 1] = pkbf(q2, q3);
            ql[mt][ks][o] = pkbf_lo(q0, q1, qh[mt][ks][o]);
            ql[mt][ks][o + 1] = pkbf_lo(q2, q3, qh[mt][ks][o + 1]);
        }
    __syncthreads();
    fillW(sm, 1, tid);
    __syncthreads();

    // ---- K gemm -> K smem (bf16 hi/lo, +bk) ----
    gemm32(smA, smW, m0, n0, lane, acc);
    store_split(sm + KOFF, acc, m0, n0, lane, bk);
    __syncthreads();
    fillW(sm, 2, tid);
    __syncthreads();

    // ---- V gemm -> V smem (bf16 hi/lo, +bv) ----
    gemm32(smA, smW, m0, n0, lane, acc);
    store_split(sm + VOFF, acc, m0, n0, lane, bv);
    __syncthreads();
    fillW(sm, 3, tid);   // Wo fill overlaps attention (disjoint smem)

    // ================= attention (all-mma) =================
    float S[2][4][4];
#pragma unroll
    for (int mt = 0; mt < 2; ++mt)
#pragma unroll
        for (int nf = 0; nf < 4; ++nf)
#pragma unroll
            for (int c = 0; c < 4; ++c) S[mt][nf][c] = 0.f;

    // scores: S = Q @ K^T ; B-frags from K rows (n = t), k-chunks = head d cols
    {
        u32 bRow[2]; int bsw[2];
#pragma unroll
        for (int ng = 0; ng < 2; ++ng) {
            int br = m0 + ng * 16 + (lane & 7) + ((lane & 16) ? 8 : 0);
            bRow[ng] = smK + br * 512; bsw[ng] = br & 7;
        }
        const int bcs = (lane >> 3) & 1;
#pragma unroll
        for (int ks = 0; ks < 2; ++ks) {
            int bch = h * 4 + 2 * ks + bcs;
            u32 kh[2][4], kl[2][4];
#pragma unroll
            for (int ng = 0; ng < 2; ++ng) {
                ldsm4(kh[ng], bRow[ng] + ((bch ^ bsw[ng]) << 4));
                ldsm4(kl[ng], bRow[ng] + (((16 + bch) ^ bsw[ng]) << 4));
            }
            // pass 1: qh @ kh
#pragma unroll
            for (int mt = 0; mt < 2; ++mt)
#pragma unroll
                for (int ng = 0; ng < 2; ++ng) {
                    mma16816(S[mt][2 * ng],     qh[mt][ks], kh[ng][0], kh[ng][1]);
                    mma16816(S[mt][2 * ng + 1], qh[mt][ks], kh[ng][2], kh[ng][3]);
                }
            // pass 2: ql @ kh
#pragma unroll
            for (int mt = 0; mt < 2; ++mt)
#pragma unroll
                for (int ng = 0; ng < 2; ++ng) {
                    mma16816(S[mt][2 * ng],     ql[mt][ks], kh[ng][0], kh[ng][1]);
                    mma16816(S[mt][2 * ng + 1], ql[mt][ks], kh[ng][2], kh[ng][3]);
                }
            // pass 3: qh @ kl
#pragma unroll
            for (int mt = 0; mt < 2; ++mt)
#pragma unroll
                for (int ng = 0; ng < 2; ++ng) {
                    mma16816(S[mt][2 * ng],     qh[mt][ks], kl[ng][0], kl[ng][1]);
                    mma16816(S[mt][2 * ng + 1], qh[mt][ks], kl[ng][2], kl[ng][3]);
                }
        }
    }

    // softmax over t (row groups of 4 lanes)
    u32 ph[2][2][4], pl[2][2][4];
    {
        float mx[2][2], iv[2][2];
#pragma unroll
        for (int mt = 0; mt < 2; ++mt)
#pragma unroll
            for (int hf = 0; hf < 2; ++hf) {
                float m = -1e30f;
#pragma unroll
                for (int nf = 0; nf < 4; ++nf)
                    m = fmaxf(m, fmaxf(S[mt][nf][hf * 2], S[mt][nf][hf * 2 + 1]));
                m = fmaxf(m, __shfl_xor_sync(~0u, m, 1));
                m = fmaxf(m, __shfl_xor_sync(~0u, m, 2));
                mx[mt][hf] = m;
            }
#pragma unroll
        for (int mt = 0; mt < 2; ++mt)
#pragma unroll
            for (int nf = 0; nf < 4; ++nf) {
                S[mt][nf][0] = __expf(S[mt][nf][0] - mx[mt][0]);
                S[mt][nf][1] = __expf(S[mt][nf][1] - mx[mt][0]);
                S[mt][nf][2] = __expf(S[mt][nf][2] - mx[mt][1]);
                S[mt][nf][3] = __expf(S[mt][nf][3] - mx[mt][1]);
            }
#pragma unroll
        for (int mt = 0; mt < 2; ++mt)
#pragma unroll
            for (int hf = 0; hf < 2; ++hf) {
                float s = 0.f;
#pragma unroll
                for (int nf = 0; nf < 4; ++nf)
                    s += S[mt][nf][hf * 2] + S[mt][nf][hf * 2 + 1];
                s += __shfl_xor_sync(~0u, s, 1);
                s += __shfl_xor_sync(~0u, s, 2);
                iv[mt][hf] = 1.f / s;
            }
#pragma unroll
        for (int mt = 0; mt < 2; ++mt)
#pragma unroll
            for (int nf = 0; nf < 4; ++nf) {
                float p0 = S[mt][nf][0] * iv[mt][0];
                float p1 = S[mt][nf][1] * iv[mt][0];
                float p2 = S[mt][nf][2] * iv[mt][1];
                float p3 = S[mt][nf][3] * iv[mt][1];
                int ks = nf >> 1, o = (nf & 1) * 2;
                ph[mt][ks][o] = pkbf(p0, p1);
                ph[mt][ks][o + 1] = pkbf(p2, p3);
                pl[mt][ks][o] = pkbf_lo(p0, p1, ph[mt][ks][o]);
                pl[mt][ks][o + 1] = pkbf_lo(p2, p3, ph[mt][ks][o + 1]);
            }
    }

    // ctx = P @ V ; V B-frags via ldmatrix.trans on V rows (k = t)
    float C[2][4][4];
#pragma unroll
    for (int mt = 0; mt < 2; ++mt)
#pragma unroll
        for (int nf = 0; nf < 4; ++nf)
#pragma unroll
            for (int c = 0; c < 4; ++c) C[mt][nf][c] = 0.f;
    {
#pragma unroll
        for (int ks = 0; ks < 2; ++ks) {
            int trow = m0 + ks * 16 + ((lane >> 3) & 1) * 8 + (lane & 7);
            u32 vrow = smV + trow * 512;
            int tsw = trow & 7;
            u32 vh[2][4], vl[2][4];
#pragma unroll
            for (int p = 0; p < 2; ++p) {
                int ch = h * 4 + 2 * p + (lane >> 4);
                ldsm4t(vh[p], vrow + ((ch ^ tsw) << 4));
                ldsm4t(vl[p], vrow + (((16 + ch) ^ tsw) << 4));
            }
            // pass 1: ph @ vh
#pragma unroll
            for (int mt = 0; mt < 2; ++mt)
#pragma unroll
                for (int p = 0; p < 2; ++p) {
                    mma16816(C[mt][2 * p],     ph[mt][ks], vh[p][0], vh[p][1]);
                    mma16816(C[mt][2 * p + 1], ph[mt][ks], vh[p][2], vh[p][3]);
                }
            // pass 2: pl @ vh
#pragma unroll
            for (int mt = 0; mt < 2; ++mt)
#pragma unroll
                for (int p = 0; p < 2; ++p) {
                    mma16816(C[mt][2 * p],     pl[mt][ks], vh[p][0], vh[p][1]);
                    mma16816(C[mt][2 * p + 1], pl[mt][ks], vh[p][2], vh[p][3]);
                }
            // pass 3: ph @ vl
#pragma unroll
            for (int mt = 0; mt < 2; ++mt)
#pragma unroll
                for (int p = 0; p < 2; ++p) {
                    mma16816(C[mt][2 * p],     ph[mt][ks], vl[p][0], vl[p][1]);
                    mma16816(C[mt][2 * p + 1], ph[mt][ks], vl[p][2], vl[p][3]);
                }
        }
    }

    // ctx -> A tile (bf16 hi/lo) at rows m0.., cols h*32..
    store_split(sm + AOFF, C, m0, n0, lane, nullptr);
    __syncthreads();

    // ---- out projection ----
    gemm32(smA, smW, m0, n0, lane, acc);

    // ---- epilogue: + bo + x residual, LayerNorm (cross-warp partials), store ----
    {
        float s1[2][2] = {{0.f, 0.f}, {0.f, 0.f}};
        float s2[2][2] = {{0.f, 0.f}, {0.f, 0.f}};
#pragma unroll
        for (int mt = 0; mt < 2; ++mt) {
            int r = m0 + mt * 16 + (lane >> 2);
#pragma unroll
            for (int nf = 0; nf < 4; ++nf) {
                int c = n0 + nf * 8 + 2 * (lane & 3);
                float2 b2 = __ldg((const float2*)(bo + c));
                float2 xa = __ldg((const float2*)(inputs + tbase + (size_t)r * 128 + c));
                float2 xb = __ldg((const float2*)(inputs + tbase + (size_t)(r + 8) * 128 + c));
                acc[mt][nf][0] += b2.x + xa.x; acc[mt][nf][1] += b2.y + xa.y;
                acc[mt][nf][2] += b2.x + xb.x; acc[mt][nf][3] += b2.y + xb.y;
                s1[mt][0] += acc[mt][nf][0] + acc[mt][nf][1];
                s2[mt][0] += acc[mt][nf][0] * acc[mt][nf][0] + acc[mt][nf][1] * acc[mt][nf][1];
                s1[mt][1] += acc[mt][nf][2] + acc[mt][nf][3];
                s2[mt][1] += acc[mt][nf][2] * acc[mt][nf][2] + acc[mt][nf][3] * acc[mt][nf][3];
            }
        }
#pragma unroll
        for (int mt = 0; mt < 2; ++mt)
#pragma unroll
            for (int hf = 0; hf < 2; ++hf) {
                s1[mt][hf] += __shfl_xor_sync(~0u, s1[mt][hf], 1);
                s1[mt][hf] += __shfl_xor_sync(~0u, s1[mt][hf], 2);
                s2[mt][hf] += __shfl_xor_sync(~0u, s2[mt][hf], 1);
                s2[mt][hf] += __shfl_xor_sync(~0u, s2[mt][hf], 2);
            }
        float2* part = (float2*)(sm + POFF);
        if ((lane & 3) == 0) {
#pragma unroll
            for (int mt = 0; mt < 2; ++mt) {
                int r = m0 + mt * 16 + (lane >> 2);
                part[r * 4 + h] = make_float2(s1[mt][0], s2[mt][0]);
                part[(r + 8) * 4 + h] = make_float2(s1[mt][1], s2[mt][1]);
            }
        }
        __syncthreads();
        float mu[2][2], rs[2][2];
#pragma unroll
        for (int mt = 0; mt < 2; ++mt)
#pragma unroll
            for (int hf = 0; hf < 2; ++hf) {
                int r = m0 + mt * 16 + (lane >> 2) + hf * 8;
                float2 p0 = part[r * 4 + 0], p1 = part[r * 4 + 1];
                float2 p2 = part[r * 4 + 2], p3 = part[r * 4 + 3];
                float S1 = p0.x + p1.x + p2.x + p3.x;
                float S2 = p0.y + p1.y + p2.y + p3.y;
                float m = S1 * (1.f / 128.f);
                float v = S2 * (1.f / 128.f) - m * m;
                mu[mt][hf] = m;
                rs[mt][hf] = rsqrtf(v + 1e-5f);
            }
#pragma unroll
        for (int mt = 0; mt < 2; ++mt) {
            int r = m0 + mt * 16 + (lane >> 2);
#pragma unroll
            for (int nf = 0; nf < 4; ++nf) {
                int c = n0 + nf * 8 + 2 * (lane & 3);
                float2 g2 = __ldg((const float2*)(gamma + c));
                float2 e2 = __ldg((const float2*)(beta + c));
                float2 o1, o2;
                o1.x = (acc[mt][nf][0] - mu[mt][0]) * rs[mt][0] * g2.x + e2.x;
                o1.y = (acc[mt][nf][1] - mu[mt][0]) * rs[mt][0] * g2.y + e2.y;
                o2.x = (acc[mt][nf][2] - mu[mt][1]) * rs[mt][1] * g2.x + e2.x;
                o2.y = (acc[mt][nf][3] - mu[mt][1]) * rs[mt][1] * g2.y + e2.y;
                *(float2*)(outp + tbase + (size_t)r * 128 + c) = o1;
                *(float2*)(outp + tbase + (size_t)(r + 8) * 128 + c) = o2;
            }
        }
    }
}

extern "C" void kernel_launch(void* const* d_in, const int* in_sizes, int n_in,
                              void* d_out, int out_size) {
    const float* inputs = (const float*)d_in[0];
    const float* Wq = (const float*)d_in[1];
    const float* bq = (const float*)d_in[2];
    const float* Wk = (const float*)d_in[3];
    const float* bk = (const float*)d_in[4];
    const float* Wv = (const float*)d_in[5];
    const float* bv = (const float*)d_in[6];
    const float* Wo = (const float*)d_in[7];
    const float* bo = (const float*)d_in[8];
    const float* gamma = (const float*)d_in[9];
    const float* beta  = (const float*)d_in[10];
    float* outp = (float*)d_out;

    prep_split<<<256, 256>>>(Wq, Wk, Wv, Wo);

    int grid = in_sizes[0] / 8192;
    cudaFuncSetAttribute(fused_attn_fa,
                         cudaFuncAttributeMaxDynamicSharedMemorySize, SMEM_BYTES);
    fused_attn_fa<<<grid, NT, SMEM_BYTES>>>(inputs, bq, bk, bv, bo, gamma, beta, outp);
}

// round 10
// speedup vs baseline: 3.5230x; 1.0426x over previous
#include <cuda_runtime.h>
#include <cuda_bf16.h>
#include <cstdint>

// Fused SelfAttention, fully tensor-core (HMMA mma.sync bf16, 3-term split).
// E=128, S=32, H=4, D=32. CTA = 128 rows (4 batches), 512 threads, grid 4096.
// Warp w -> tile (m0=(w>>2)*32, n0=(w&3)*32) == attention block (batch, head).
// R9: 16 warps/SM; K and V share one smem buffer (phase-reordered:
// Q gemm -> K gemm -> scores -> V gemm -> ctx); Wv fill overlaps scores,
// Wo fill overlaps ctx.
//
// SMEM:
//   A  @0      : bf16 [128][256] (hi|lo), 512B rows, 16B-chunk xor swizzle. 64KB
//   W  @65536  : bf16 [128][256] (hi|lo) swizzled weight image.            64KB
//   KV @131072 : like A; holds K, then V.                                  64KB
//   LN partials @196608 : float2[128][4].                                   4KB

typedef unsigned int u32;

#define NT 512
#define AOFF 0
#define WOFF 65536
#define KVOFF 131072
#define POFF 196608
#define SMEM_BYTES 200704
#define QSCALE 0.17677669529663687f

__device__ __align__(16) unsigned char g_Wpk[262144];

// ---------------- prep: split W into bf16 hi/lo swizzled smem images ----------
__global__ void prep_split(const float* __restrict__ Wq, const float* __restrict__ Wk,
                           const float* __restrict__ Wv, const float* __restrict__ Wo) {
    int id = blockIdx.x * blockDim.x + threadIdx.x;   // u32 words
    const float* W = (id < 16384) ? Wq : (id < 32768) ? Wk : (id < 49152) ? Wv : Wo;
    int rem = id & 16383;
    int f = rem >> 7;
    int w = rem & 127;
    int pc = w >> 2, j = w & 3;
    int lc = pc ^ (f & 7);
    int k0 = lc * 8 + j * 2;
    __nv_bfloat16 v[2];
#pragma unroll
    for (int i = 0; i < 2; ++i) {
        int kc = k0 + i;
        if (kc < 128) {
            v[i] = __float2bfloat16_rn(W[f * 128 + kc]);
        } else {
            float x = W[f * 128 + (kc - 128)];
            __nv_bfloat16 h = __float2bfloat16_rn(x);
            v[i] = __float2bfloat16_rn(x - __bfloat162float(h));
        }
    }
    __nv_bfloat162 p = __halves2bfloat162(v[0], v[1]);
    ((u32*)g_Wpk)[id] = *(u32*)&p;
}

// ---------------- helpers ----------------
__device__ __forceinline__ u32 s2u(const void* p) {
    u32 a;
    asm("{ .reg .u64 t; cvta.to.shared.u64 t, %1; cvt.u32.u64 %0, t; }" : "=r"(a) : "l"(p));
    return a;
}
__device__ __forceinline__ void ldsm4(u32* r, u32 a) {
    asm volatile("ldmatrix.sync.aligned.m8n8.x4.shared.b16 {%0,%1,%2,%3}, [%4];"
                 : "=r"(r[0]), "=r"(r[1]), "=r"(r[2]), "=r"(r[3]) : "r"(a));
}
__device__ __forceinline__ void ldsm4t(u32* r, u32 a) {
    asm volatile("ldmatrix.sync.aligned.m8n8.x4.trans.shared.b16 {%0,%1,%2,%3}, [%4];"
                 : "=r"(r[0]), "=r"(r[1]), "=r"(r[2]), "=r"(r[3]) : "r"(a));
}
__device__ __forceinline__ void mma16816(float* c, const u32* a, u32 b0, u32 b1) {
    asm volatile(
        "mma.sync.aligned.m16n8k16.row.col.f32.bf16.bf16.f32 "
        "{%0,%1,%2,%3}, {%4,%5,%6,%7}, {%8,%9}, {%0,%1,%2,%3};"
        : "+f"(c[0]), "+f"(c[1]), "+f"(c[2]), "+f"(c[3])
        : "r"(a[0]), "r"(a[1]), "r"(a[2]), "r"(a[3]), "r"(b0), "r"(b1));
}
__device__ __forceinline__ u32 pkbf(float a, float b) {
    __nv_bfloat162 t = __halves2bfloat162(__float2bfloat16_rn(a), __float2bfloat16_rn(b));
    return *(u32*)&t;
}
__device__ __forceinline__ u32 pkbf_lo(float a, float b, u32 hi) {
    __nv_bfloat162 h = *(__nv_bfloat162*)&hi;
    return pkbf(a - __bfloat162float(h.x), b - __bfloat162float(h.y));
}

// C[m0:+32][n0:+32] = A(128x128 hi/lo) @ W^T(128x128 hi/lo), 3-term split.
__device__ __forceinline__ void gemm32(u32 smA, u32 smW, int m0, int n0, int lane,
                                       float acc[2][4][4]) {
    u32 aRow[2]; int asw[2];
#pragma unroll
    for (int mt = 0; mt < 2; ++mt) {
        int ar = m0 + mt * 16 + (lane & 7) + ((lane & 8) ? 8 : 0);
        aRow[mt] = smA + ar * 512; asw[mt] = ar & 7;
    }
    const int acs = lane >> 4;
    u32 bRow[2]; int bsw[2];
#pragma unroll
    for (int ng = 0; ng < 2; ++ng) {
        int br = n0 + ng * 16 + (lane & 7) + ((lane & 16) ? 8 : 0);
        bRow[ng] = smW + br * 512; bsw[ng] = br & 7;
    }
    const int bcs = (lane >> 3) & 1;
#pragma unroll
    for (int mt = 0; mt < 2; ++mt)
#pragma unroll
        for (int nf = 0; nf < 4; ++nf)
#pragma unroll
            for (int c = 0; c < 4; ++c) acc[mt][nf][c] = 0.f;

#pragma unroll
    for (int j = 0; j < 8; ++j) {
        const int ach = 2 * j + acs, bch = 2 * j + bcs;
        u32 ah[2][4], al[2][4], bh[2][4], bl[2][4];
#pragma unroll
        for (int mt = 0; mt < 2; ++mt) {
            ldsm4(ah[mt], aRow[mt] + ((ach ^ asw[mt]) << 4));
            ldsm4(al[mt], aRow[mt] + (((16 + ach) ^ asw[mt]) << 4));
        }
#pragma unroll
        for (int ng = 0; ng < 2; ++ng) {
            ldsm4(bh[ng], bRow[ng] + ((bch ^ bsw[ng]) << 4));
            ldsm4(bl[ng], bRow[ng] + (((16 + bch) ^ bsw[ng]) << 4));
        }
#pragma unroll
        for (int mt = 0; mt < 2; ++mt)
#pragma unroll
            for (int ng = 0; ng < 2; ++ng) {
                mma16816(acc[mt][2 * ng],     ah[mt], bh[ng][0], bh[ng][1]);
                mma16816(acc[mt][2 * ng + 1], ah[mt], bh[ng][2], bh[ng][3]);
            }
#pragma unroll
        for (int mt = 0; mt < 2; ++mt)
#pragma unroll
            for (int ng = 0; ng < 2; ++ng) {
                mma16816(acc[mt][2 * ng],     al[mt], bh[ng][0], bh[ng][1]);
                mma16816(acc[mt][2 * ng + 1], al[mt], bh[ng][2], bh[ng][3]);
            }
#pragma unroll
        for (int mt = 0; mt < 2; ++mt)
#pragma unroll
            for (int ng = 0; ng < 2; ++ng) {
                mma16816(acc[mt][2 * ng],     ah[mt], bl[ng][0], bl[ng][1]);
                mma16816(acc[mt][2 * ng + 1], ah[mt], bl[ng][2], bl[ng][3]);
            }
    }
}

// c-frags (+optional bias) -> bf16 hi/lo into an A-style [128][256] image.
__device__ __forceinline__ void store_split(char* dst, const float acc[2][4][4],
                                            int m0, int n0, int lane,
                                            const float* bias) {
#pragma unroll
    for (int mt = 0; mt < 2; ++mt) {
        int r = m0 + mt * 16 + (lane >> 2);
        char* row0 = dst + r * 512;
        char* row1 = dst + (r + 8) * 512;
        int sw = r & 7;
#pragma unroll
        for (int nf = 0; nf < 4; ++nf) {
            int c = n0 + nf * 8 + 2 * (lane & 3);
            float v0 = acc[mt][nf][0], v1 = acc[mt][nf][1];
            float v2 = acc[mt][nf][2], v3 = acc[mt][nf][3];
            if (bias) {
                float2 b2 = __ldg((const float2*)(bias + c));
                v0 += b2.x; v1 += b2.y; v2 += b2.x; v3 += b2.y;
            }
            u32 h01 = pkbf(v0, v1), l01 = pkbf_lo(v0, v1, h01);
            u32 h23 = pkbf(v2, v3), l23 = pkbf_lo(v2, v3, h23);
            int ch = c >> 3, bo_ = (c & 7) * 2;
            *(u32*)(row0 + ((ch ^ sw) << 4) + bo_) = h01;
            *(u32*)(row0 + (((16 + ch) ^ sw) << 4) + bo_) = l01;
            *(u32*)(row1 + ((ch ^ sw) << 4) + bo_) = h23;
            *(u32*)(row1 + (((16 + ch) ^ sw) << 4) + bo_) = l23;
        }
    }
}

__device__ __forceinline__ void fillW(char* sm, int g, int tid) {
    const uint4* src = (const uint4*)g_Wpk + g * 4096;
    uint4* dst = (uint4*)(sm + WOFF);
#pragma unroll
    for (int p = 0; p < 8; ++p) dst[p * NT + tid] = __ldg(src + p * NT + tid);
}

// ---------------- main kernel ----------------
__global__ void __launch_bounds__(NT, 1)
fused_attn_fa(const float* __restrict__ inputs,
              const float* __restrict__ bq, const float* __restrict__ bk,
              const float* __restrict__ bv, const float* __restrict__ bo,
              const float* __restrict__ gamma, const float* __restrict__ beta,
              float* __restrict__ outp)
{
    extern __shared__ char sm[];
    const int tid = threadIdx.x;
    const int lane = tid & 31;
    const int warp = tid >> 5;
    const u32 smb = s2u(sm);
    const u32 smA = smb + AOFF, smW = smb + WOFF;
    const u32 smKV = smb + KVOFF;
    const int m0 = (warp >> 2) * 32;    // batch block (rows), 0..96
    const int n0 = (warp & 3) * 32;     // head block (cols)
    const int h = warp & 3;
    const size_t tbase = (size_t)blockIdx.x * 16384;

    // ---- fill A (x split hi/lo): 128 rows x 32 float4 ----
    {
        const float4* gx = (const float4*)(inputs + tbase);
#pragma unroll
        for (int p = 0; p < 8; ++p) {
            int e = p * NT + tid;
            int row = e >> 5, c4 = e & 31;
            float4 v = __ldg(gx + e);
            float hx = __bfloat162float(__float2bfloat16_rn(v.x));
            float hy = __bfloat162float(__float2bfloat16_rn(v.y));
            float hz = __bfloat162float(__float2bfloat16_rn(v.z));
            float hw = __bfloat162float(__float2bfloat16_rn(v.w));
            uint2 hi = make_uint2(pkbf(v.x, v.y), pkbf(v.z, v.w));
            uint2 lo = make_uint2(pkbf(v.x - hx, v.y - hy), pkbf(v.z - hz, v.w - hw));
            char* arow = sm + AOFF + row * 512;
            int ch = c4 >> 1, off8 = (c4 & 1) * 8, sw = row & 7;
            *(uint2*)(arow + ((ch ^ sw) << 4) + off8) = hi;
            *(uint2*)(arow + (((16 + ch) ^ sw) << 4) + off8) = lo;
        }
    }
    fillW(sm, 0, tid);
    __syncthreads();

    float acc[2][4][4];

    // ---- Q gemm; keep as bf16 a-frags in registers (bias+scale folded) ----
    gemm32(smA, smW, m0, n0, lane, acc);
    u32 qh[2][2][4], ql[2][2][4];
#pragma unroll
    for (int mt = 0; mt < 2; ++mt)
#pragma unroll
        for (int nf = 0; nf < 4; ++nf) {
            int c = n0 + nf * 8 + 2 * (lane & 3);
            float2 b2 = __ldg((const float2*)(bq + c));
            float q0 = (acc[mt][nf][0] + b2.x) * QSCALE;
            float q1 = (acc[mt][nf][1] + b2.y) * QSCALE;
            float q2 = (acc[mt][nf][2] + b2.x) * QSCALE;
            float q3 = (acc[mt][nf][3] + b2.y) * QSCALE;
            int ks = nf >> 1, o = (nf & 1) * 2;
            qh[mt][ks][o] = pkbf(q0, q1);
            qh[mt][ks][o + 1] = pkbf(q2, q3);
            ql[mt][ks][o] = pkbf_lo(q0, q1, qh[mt][ks][o]);
            ql[mt][ks][o + 1] = pkbf_lo(q2, q3, qh[mt][ks][o + 1]);
        }
    __syncthreads();
    fillW(sm, 1, tid);
    __syncthreads();

    // ---- K gemm -> KV smem (bf16 hi/lo, +bk) ----
    gemm32(smA, smW, m0, n0, lane, acc);
    store_split(sm + KVOFF, acc, m0, n0, lane, bk);
    __syncthreads();

    // ---- Wv fill overlaps scores ----
    fillW(sm, 2, tid);

    // scores: S = Q @ K^T ; B-frags from K rows (n = t)
    float S[2][4][4];
#pragma unroll
    for (int mt = 0; mt < 2; ++mt)
#pragma unroll
        for (int nf = 0; nf < 4; ++nf)
#pragma unroll
            for (int c = 0; c < 4; ++c) S[mt][nf][c] = 0.f;
    {
        u32 bRow[2]; int bsw[2];
#pragma unroll
        for (int ng = 0; ng < 2; ++ng) {
            int br = m0 + ng * 16 + (lane & 7) + ((lane & 16) ? 8 : 0);
            bRow[ng] = smKV + br * 512; bsw[ng] = br & 7;
        }
        const int bcs = (lane >> 3) & 1;
#pragma unroll
        for (int ks = 0; ks < 2; ++ks) {
            int bch = h * 4 + 2 * ks + bcs;
            u32 kh[2][4], kl[2][4];
#pragma unroll
            for (int ng = 0; ng < 2; ++ng) {
                ldsm4(kh[ng], bRow[ng] + ((bch ^ bsw[ng]) << 4));
                ldsm4(kl[ng], bRow[ng] + (((16 + bch) ^ bsw[ng]) << 4));
            }
#pragma unroll
            for (int mt = 0; mt < 2; ++mt)
#pragma unroll
                for (int ng = 0; ng < 2; ++ng) {
                    mma16816(S[mt][2 * ng],     qh[mt][ks], kh[ng][0], kh[ng][1]);
                    mma16816(S[mt][2 * ng + 1], qh[mt][ks], kh[ng][2], kh[ng][3]);
                }
#pragma unroll
            for (int mt = 0; mt < 2; ++mt)
#pragma unroll
                for (int ng = 0; ng < 2; ++ng) {
                    mma16816(S[mt][2 * ng],     ql[mt][ks], kh[ng][0], kh[ng][1]);
                    mma16816(S[mt][2 * ng + 1], ql[mt][ks], kh[ng][2], kh[ng][3]);
                }
#pragma unroll
            for (int mt = 0; mt < 2; ++mt)
#pragma unroll
                for (int ng = 0; ng < 2; ++ng) {
                    mma16816(S[mt][2 * ng],     qh[mt][ks], kl[ng][0], kl[ng][1]);
                    mma16816(S[mt][2 * ng + 1], qh[mt][ks], kl[ng][2], kl[ng][3]);
                }
        }
    }
    __syncthreads();   // everyone done reading K; Wv ready

    // ---- V gemm -> KV smem (bf16 hi/lo, +bv) ----
    gemm32(smA, smW, m0, n0, lane, acc);
    store_split(sm + KVOFF, acc, m0, n0, lane, bv);
    __syncthreads();

    // ---- Wo fill overlaps softmax+ctx ----
    fillW(sm, 3, tid);

    // softmax over t (row groups of 4 lanes)
    u32 ph[2][2][4], pl[2][2][4];
    {
        float mx[2][2], iv[2][2];
#pragma unroll
        for (int mt = 0; mt < 2; ++mt)
#pragma unroll
            for (int hf = 0; hf < 2; ++hf) {
                float m = -1e30f;
#pragma unroll
                for (int nf = 0; nf < 4; ++nf)
                    m = fmaxf(m, fmaxf(S[mt][nf][hf * 2], S[mt][nf][hf * 2 + 1]));
                m = fmaxf(m, __shfl_xor_sync(~0u, m, 1));
                m = fmaxf(m, __shfl_xor_sync(~0u, m, 2));
                mx[mt][hf] = m;
            }
#pragma unroll
        for (int mt = 0; mt < 2; ++mt)
#pragma unroll
            for (int nf = 0; nf < 4; ++nf) {
                S[mt][nf][0] = __expf(S[mt][nf][0] - mx[mt][0]);
                S[mt][nf][1] = __expf(S[mt][nf][1] - mx[mt][0]);
                S[mt][nf][2] = __expf(S[mt][nf][2] - mx[mt][1]);
                S[mt][nf][3] = __expf(S[mt][nf][3] - mx[mt][1]);
            }
#pragma unroll
        for (int mt = 0; mt < 2; ++mt)
#pragma unroll
            for (int hf = 0; hf < 2; ++hf) {
                float s = 0.f;
#pragma unroll
                for (int nf = 0; nf < 4; ++nf)
                    s += S[mt][nf][hf * 2] + S[mt][nf][hf * 2 + 1];
                s += __shfl_xor_sync(~0u, s, 1);
                s += __shfl_xor_sync(~0u, s, 2);
                iv[mt][hf] = 1.f / s;
            }
#pragma unroll
        for (int mt = 0; mt < 2; ++mt)
#pragma unroll
            for (int nf = 0; nf < 4; ++nf) {
                float p0 = S[mt][nf][0] * iv[mt][0];
                float p1 = S[mt][nf][1] * iv[mt][0];
                float p2 = S[mt][nf][2] * iv[mt][1];
                float p3 = S[mt][nf][3] * iv[mt][1];
                int ks = nf >> 1, o = (nf & 1) * 2;
                ph[mt][ks][o] = pkbf(p0, p1);
                ph[mt][ks][o + 1] = pkbf(p2, p3);
                pl[mt][ks][o] = pkbf_lo(p0, p1, ph[mt][ks][o]);
                pl[mt][ks][o + 1] = pkbf_lo(p2, p3, ph[mt][ks][o + 1]);
            }
    }

    // ctx = P @ V ; V B-frags via ldmatrix.trans on V rows (k = t)
    float C[2][4][4];
#pragma unroll
    for (int mt = 0; mt < 2; ++mt)
#pragma unroll
        for (int nf = 0; nf < 4; ++nf)
#pragma unroll
            for (int c = 0; c < 4; ++c) C[mt][nf][c] = 0.f;
    {
#pragma unroll
        for (int ks = 0; ks < 2; ++ks) {
            int trow = m0 + ks * 16 + ((lane >> 3) & 1) * 8 + (lane & 7);
            u32 vrow = smKV + trow * 512;
            int tsw = trow & 7;
            u32 vh[2][4], vl[2][4];
#pragma unroll
            for (int p = 0; p < 2; ++p) {
                int ch = h * 4 + 2 * p + (lane >> 4);
                ldsm4t(vh[p], vrow + ((ch ^ tsw) << 4));
                ldsm4t(vl[p], vrow + (((16 + ch) ^ tsw) << 4));
            }
#pragma unroll
            for (int mt = 0; mt < 2; ++mt)
#pragma unroll
                for (int p = 0; p < 2; ++p) {
                    mma16816(C[mt][2 * p],     ph[mt][ks], vh[p][0], vh[p][1]);
                    mma16816(C[mt][2 * p + 1], ph[mt][ks], vh[p][2], vh[p][3]);
                }
#pragma unroll
            for (int mt = 0; mt < 2; ++mt)
#pragma unroll
                for (int p = 0; p < 2; ++p) {
                    mma16816(C[mt][2 * p],     pl[mt][ks], vh[p][0], vh[p][1]);
                    mma16816(C[mt][2 * p + 1], pl[mt][ks], vh[p][2], vh[p][3]);
                }
#pragma unroll
            for (int mt = 0; mt < 2; ++mt)
#pragma unroll
                for (int p = 0; p < 2; ++p) {
                    mma16816(C[mt][2 * p],     ph[mt][ks], vl[p][0], vl[p][1]);
                    mma16816(C[mt][2 * p + 1], ph[mt][ks], vl[p][2], vl[p][3]);
                }
        }
    }

    // ctx -> A tile (bf16 hi/lo) at rows m0.., cols h*32..
    store_split(sm + AOFF, C, m0, n0, lane, nullptr);
    __syncthreads();   // ctx in A + Wo ready

    // ---- out projection ----
    gemm32(smA, smW, m0, n0, lane, acc);

    // ---- epilogue: + bo + x residual, LayerNorm (cross-warp partials), store ----
    {
        float s1[2][2] = {{0.f, 0.f}, {0.f, 0.f}};
        float s2[2][2] = {{0.f, 0.f}, {0.f, 0.f}};
#pragma unroll
        for (int mt = 0; mt < 2; ++mt) {
            int r = m0 + mt * 16 + (lane >> 2);
#pragma unroll
            for (int nf = 0; nf < 4; ++nf) {
                int c = n0 + nf * 8 + 2 * (lane & 3);
                float2 b2 = __ldg((const float2*)(bo + c));
                float2 xa = __ldg((const float2*)(inputs + tbase + (size_t)r * 128 + c));
                float2 xb = __ldg((const float2*)(inputs + tbase + (size_t)(r + 8) * 128 + c));
                acc[mt][nf][0] += b2.x + xa.x; acc[mt][nf][1] += b2.y + xa.y;
                acc[mt][nf][2] += b2.x + xb.x; acc[mt][nf][3] += b2.y + xb.y;
                s1[mt][0] += acc[mt][nf][0] + acc[mt][nf][1];
                s2[mt][0] += acc[mt][nf][0] * acc[mt][nf][0] + acc[mt][nf][1] * acc[mt][nf][1];
                s1[mt][1] += acc[mt][nf][2] + acc[mt][nf][3];
                s2[mt][1] += acc[mt][nf][2] * acc[mt][nf][2] + acc[mt][nf][3] * acc[mt][nf][3];
            }
        }
#pragma unroll
        for (int mt = 0; mt < 2; ++mt)
#pragma unroll
            for (int hf = 0; hf < 2; ++hf) {
                s1[mt][hf] += __shfl_xor_sync(~0u, s1[mt][hf], 1);
                s1[mt][hf] += __shfl_xor_sync(~0u, s1[mt][hf], 2);
                s2[mt][hf] += __shfl_xor_sync(~0u, s2[mt][hf], 1);
                s2[mt][hf] += __shfl_xor_sync(~0u, s2[mt][hf], 2);
            }
        float2* part = (float2*)(sm + POFF);
        if ((lane & 3) == 0) {
#pragma unroll
            for (int mt = 0; mt < 2; ++mt) {
                int r = m0 + mt * 16 + (lane >> 2);
                part[r * 4 + h] = make_float2(s1[mt][0], s2[mt][0]);
                part[(r + 8) * 4 + h] = make_float2(s1[mt][1], s2[mt][1]);
            }
        }
        __syncthreads();
        float mu[2][2], rs[2][2];
#pragma unroll
        for (int mt = 0; mt < 2; ++mt)
#pragma unroll
            for (int hf = 0; hf < 2; ++hf) {
                int r = m0 + mt * 16 + (lane >> 2) + hf * 8;
                float2 p0 = part[r * 4 + 0], p1 = part[r * 4 + 1];
                float2 p2 = part[r * 4 + 2], p3 = part[r * 4 + 3];
                float S1 = p0.x + p1.x + p2.x + p3.x;
                float S2 = p0.y + p1.y + p2.y + p3.y;
                float m = S1 * (1.f / 128.f);
                float v = S2 * (1.f / 128.f) - m * m;
                mu[mt][hf] = m;
                rs[mt][hf] = rsqrtf(v + 1e-5f);
            }
#pragma unroll
        for (int mt = 0; mt < 2; ++mt) {
            int r = m0 + mt * 16 + (lane >> 2);
#pragma unroll
            for (int nf = 0; nf < 4; ++nf) {
                int c = n0 + nf * 8 + 2 * (lane & 3);
                float2 g2 = __ldg((const float2*)(gamma + c));
                float2 e2 = __ldg((const float2*)(beta + c));
                float2 o1, o2;
                o1.x = (acc[mt][nf][0] - mu[mt][0]) * rs[mt][0] * g2.x + e2.x;
                o1.y = (acc[mt][nf][1] - mu[mt][0]) * rs[mt][0] * g2.y + e2.y;
                o2.x = (acc[mt][nf][2] - mu[mt][1]) * rs[mt][1] * g2.x + e2.x;
                o2.y = (acc[mt][nf][3] - mu[mt][1]) * rs[mt][1] * g2.y + e2.y;
                *(float2*)(outp + tbase + (size_t)r * 128 + c) = o1;
                *(float2*)(outp + tbase + (size_t)(r + 8) * 128 + c) = o2;
            }
        }
    }
}

extern "C" void kernel_launch(void* const* d_in, const int* in_sizes, int n_in,
                              void* d_out, int out_size) {
    const float* inputs = (const float*)d_in[0];
    const float* Wq = (const float*)d_in[1];
    const float* bq = (const float*)d_in[2];
    const float* Wk = (const float*)d_in[3];
    const float* bk = (const float*)d_in[4];
    const float* Wv = (const float*)d_in[5];
    const float* bv = (const float*)d_in[6];
    const float* Wo = (const float*)d_in[7];
    const float* bo = (const float*)d_in[8];
    const float* gamma = (const float*)d_in[9];
    const float* beta  = (const float*)d_in[10];
    float* outp = (float*)d_out;

    prep_split<<<256, 256>>>(Wq, Wk, Wv, Wo);

    int grid = in_sizes[0] / 16384;   // 128 rows * 128 cols per CTA
    cudaFuncSetAttribute(fused_attn_fa,
                         cudaFuncAttributeMaxDynamicSharedMemorySize, SMEM_BYTES);
    fused_attn_fa<<<grid, NT, SMEM_BYTES>>>(inputs, bq, bk, bv, bo, gamma, beta, outp);
}

// round 11
// speedup vs baseline: 3.6011x; 1.0222x over previous
#include <cuda_runtime.h>
#include <cuda_bf16.h>
#include <cstdint>

// Fused SelfAttention, fully tensor-core (HMMA mma.sync bf16, 3-term split).
// E=128, S=32, H=4, D=32. CTA = 128 rows (4 batches), 512 threads, grid 4096.
// Warp w -> tile (m0=(w>>2)*32, n0=(w&3)*32) == attention block (batch, head).
// R10: attention is fully register-resident. K gemm c-frags repack directly
// into score B-frags; V gemm c-frags transpose via movmatrix into ctx B-frags.
// No K/V smem. Two W buffers ping-pong so weight fills overlap gemms.
//
// SMEM:
//   A  @0      : bf16 [128][256] (hi|lo), 512B rows, 16B-chunk xor swizzle. 64KB
//   W0 @65536  : bf16 [128][256] swizzled weight image.                    64KB
//   W1 @131072 : second weight buffer (ping-pong).                         64KB
//   LN partials @196608 : float2[128][4].                                   4KB

typedef unsigned int u32;

#define NT 512
#define AOFF 0
#define W0OFF 65536
#define W1OFF 131072
#define POFF 196608
#define SMEM_BYTES 200704
#define QSCALE 0.17677669529663687f

__device__ __align__(16) unsigned char g_Wpk[262144];

// ---------------- prep: split W into bf16 hi/lo swizzled smem images ----------
__global__ void prep_split(const float* __restrict__ Wq, const float* __restrict__ Wk,
                           const float* __restrict__ Wv, const float* __restrict__ Wo) {
    int id = blockIdx.x * blockDim.x + threadIdx.x;   // u32 words
    const float* W = (id < 16384) ? Wq : (id < 32768) ? Wk : (id < 49152) ? Wv : Wo;
    int rem = id & 16383;
    int f = rem >> 7;
    int w = rem & 127;
    int pc = w >> 2, j = w & 3;
    int lc = pc ^ (f & 7);
    int k0 = lc * 8 + j * 2;
    __nv_bfloat16 v[2];
#pragma unroll
    for (int i = 0; i < 2; ++i) {
        int kc = k0 + i;
        if (kc < 128) {
            v[i] = __float2bfloat16_rn(W[f * 128 + kc]);
        } else {
            float x = W[f * 128 + (kc - 128)];
            __nv_bfloat16 h = __float2bfloat16_rn(x);
            v[i] = __float2bfloat16_rn(x - __bfloat162float(h));
        }
    }
    __nv_bfloat162 p = __halves2bfloat162(v[0], v[1]);
    ((u32*)g_Wpk)[id] = *(u32*)&p;
}

// ---------------- helpers ----------------
__device__ __forceinline__ u32 s2u(const void* p) {
    u32 a;
    asm("{ .reg .u64 t; cvta.to.shared.u64 t, %1; cvt.u32.u64 %0, t; }" : "=r"(a) : "l"(p));
    return a;
}
__device__ __forceinline__ void ldsm4(u32* r, u32 a) {
    asm volatile("ldmatrix.sync.aligned.m8n8.x4.shared.b16 {%0,%1,%2,%3}, [%4];"
                 : "=r"(r[0]), "=r"(r[1]), "=r"(r[2]), "=r"(r[3]) : "r"(a));
}
__device__ __forceinline__ u32 movm_t(u32 s) {
    u32 d;
    asm("movmatrix.sync.aligned.m8n8.trans.b16 %0, %1;" : "=r"(d) : "r"(s));
    return d;
}
__device__ __forceinline__ void mma16816(float* c, const u32* a, u32 b0, u32 b1) {
    asm volatile(
        "mma.sync.aligned.m16n8k16.row.col.f32.bf16.bf16.f32 "
        "{%0,%1,%2,%3}, {%4,%5,%6,%7}, {%8,%9}, {%0,%1,%2,%3};"
        : "+f"(c[0]), "+f"(c[1]), "+f"(c[2]), "+f"(c[3])
        : "r"(a[0]), "r"(a[1]), "r"(a[2]), "r"(a[3]), "r"(b0), "r"(b1));
}
__device__ __forceinline__ u32 pkbf(float a, float b) {
    __nv_bfloat162 t = __halves2bfloat162(__float2bfloat16_rn(a), __float2bfloat16_rn(b));
    return *(u32*)&t;
}
__device__ __forceinline__ u32 pkbf_lo(float a, float b, u32 hi) {
    __nv_bfloat162 h = *(__nv_bfloat162*)&hi;
    return pkbf(a - __bfloat162float(h.x), b - __bfloat162float(h.y));
}

// C[m0:+32][n0:+32] = A(128x128 hi/lo) @ W^T(128x128 hi/lo), 3-term split.
__device__ __forceinline__ void gemm32(u32 smA, u32 smW, int m0, int n0, int lane,
                                       float acc[2][4][4]) {
    u32 aRow[2]; int asw[2];
#pragma unroll
    for (int mt = 0; mt < 2; ++mt) {
        int ar = m0 + mt * 16 + (lane & 7) + ((lane & 8) ? 8 : 0);
        aRow[mt] = smA + ar * 512; asw[mt] = ar & 7;
    }
    const int acs = lane >> 4;
    u32 bRow[2]; int bsw[2];
#pragma unroll
    for (int ng = 0; ng < 2; ++ng) {
        int br = n0 + ng * 16 + (lane & 7) + ((lane & 16) ? 8 : 0);
        bRow[ng] = smW + br * 512; bsw[ng] = br & 7;
    }
    const int bcs = (lane >> 3) & 1;
#pragma unroll
    for (int mt = 0; mt < 2; ++mt)
#pragma unroll
        for (int nf = 0; nf < 4; ++nf)
#pragma unroll
            for (int c = 0; c < 4; ++c) acc[mt][nf][c] = 0.f;

#pragma unroll
    for (int j = 0; j < 8; ++j) {
        const int ach = 2 * j + acs, bch = 2 * j + bcs;
        u32 ah[2][4], al[2][4], bh[2][4], bl[2][4];
#pragma unroll
        for (int mt = 0; mt < 2; ++mt) {
            ldsm4(ah[mt], aRow[mt] + ((ach ^ asw[mt]) << 4));
            ldsm4(al[mt], aRow[mt] + (((16 + ach) ^ asw[mt]) << 4));
        }
#pragma unroll
        for (int ng = 0; ng < 2; ++ng) {
            ldsm4(bh[ng], bRow[ng] + ((bch ^ bsw[ng]) << 4));
            ldsm4(bl[ng], bRow[ng] + (((16 + bch) ^ bsw[ng]) << 4));
        }
#pragma unroll
        for (int mt = 0; mt < 2; ++mt)
#pragma unroll
            for (int ng = 0; ng < 2; ++ng) {
                mma16816(acc[mt][2 * ng],     ah[mt], bh[ng][0], bh[ng][1]);
                mma16816(acc[mt][2 * ng + 1], ah[mt], bh[ng][2], bh[ng][3]);
            }
#pragma unroll
        for (int mt = 0; mt < 2; ++mt)
#pragma unroll
            for (int ng = 0; ng < 2; ++ng) {
                mma16816(acc[mt][2 * ng],     al[mt], bh[ng][0], bh[ng][1]);
                mma16816(acc[mt][2 * ng + 1], al[mt], bh[ng][2], bh[ng][3]);
            }
#pragma unroll
        for (int mt = 0; mt < 2; ++mt)
#pragma unroll
            for (int ng = 0; ng < 2; ++ng) {
                mma16816(acc[mt][2 * ng],     ah[mt], bl[ng][0], bl[ng][1]);
                mma16816(acc[mt][2 * ng + 1], ah[mt], bl[ng][2], bl[ng][3]);
            }
    }
}

// c-frags -> bf16 hi/lo into an A-style [128][256] image (used for ctx only).
__device__ __forceinline__ void store_split(char* dst, const float acc[2][4][4],
                                            int m0, int n0, int lane) {
#pragma unroll
    for (int mt = 0; mt < 2; ++mt) {
        int r = m0 + mt * 16 + (lane >> 2);
        char* row0 = dst + r * 512;
        char* row1 = dst + (r + 8) * 512;
        int sw = r & 7;
#pragma unroll
        for (int nf = 0; nf < 4; ++nf) {
            int c = n0 + nf * 8 + 2 * (lane & 3);
            float v0 = acc[mt][nf][0], v1 = acc[mt][nf][1];
            float v2 = acc[mt][nf][2], v3 = acc[mt][nf][3];
            u32 h01 = pkbf(v0, v1), l01 = pkbf_lo(v0, v1, h01);
            u32 h23 = pkbf(v2, v3), l23 = pkbf_lo(v2, v3, h23);
            int ch = c >> 3, bo_ = (c & 7) * 2;
            *(u32*)(row0 + ((ch ^ sw) << 4) + bo_) = h01;
            *(u32*)(row0 + (((16 + ch) ^ sw) << 4) + bo_) = l01;
            *(u32*)(row1 + ((ch ^ sw) << 4) + bo_) = h23;
            *(u32*)(row1 + (((16 + ch) ^ sw) << 4) + bo_) = l23;
        }
    }
}

__device__ __forceinline__ void fillW(char* dstW, int g, int tid) {
    const uint4* src = (const uint4*)g_Wpk + g * 4096;
    uint4* dst = (uint4*)dstW;
#pragma unroll
    for (int p = 0; p < 8; ++p) dst[p * NT + tid] = __ldg(src + p * NT + tid);
}

// ---------------- main kernel ----------------
__global__ void __launch_bounds__(NT, 1)
fused_attn_fa(const float* __restrict__ inputs,
              const float* __restrict__ bq, const float* __restrict__ bk,
              const float* __restrict__ bv, const float* __restrict__ bo,
              const float* __restrict__ gamma, const float* __restrict__ beta,
              float* __restrict__ outp)
{
    extern __shared__ char sm[];
    const int tid = threadIdx.x;
    const int lane = tid & 31;
    const int warp = tid >> 5;
    const u32 smb = s2u(sm);
    const u32 smA = smb + AOFF, smW0 = smb + W0OFF, smW1 = smb + W1OFF;
    const int m0 = (warp >> 2) * 32;    // batch block (rows)
    const int n0 = (warp & 3) * 32;     // head block (cols)
    const int h = warp & 3;
    const size_t tbase = (size_t)blockIdx.x * 16384;

    // ---- fill A (x split hi/lo) + Wq -> W0 ----
    {
        const float4* gx = (const float4*)(inputs + tbase);
#pragma unroll
        for (int p = 0; p < 8; ++p) {
            int e = p * NT + tid;
            int row = e >> 5, c4 = e & 31;
            float4 v = __ldg(gx + e);
            float hx = __bfloat162float(__float2bfloat16_rn(v.x));
            float hy = __bfloat162float(__float2bfloat16_rn(v.y));
            float hz = __bfloat162float(__float2bfloat16_rn(v.z));
            float hw = __bfloat162float(__float2bfloat16_rn(v.w));
            uint2 hi = make_uint2(pkbf(v.x, v.y), pkbf(v.z, v.w));
            uint2 lo = make_uint2(pkbf(v.x - hx, v.y - hy), pkbf(v.z - hz, v.w - hw));
            char* arow = sm + AOFF + row * 512;
            int ch = c4 >> 1, off8 = (c4 & 1) * 8, sw = row & 7;
            *(uint2*)(arow + ((ch ^ sw) << 4) + off8) = hi;
            *(uint2*)(arow + (((16 + ch) ^ sw) << 4) + off8) = lo;
        }
    }
    fillW(sm + W0OFF, 0, tid);
    __syncthreads();

    float acc[2][4][4];

    // ======== phase A: Wk fill (W1) overlaps Q gemm (W0) ========
    fillW(sm + W1OFF, 1, tid);
    gemm32(smA, smW0, m0, n0, lane, acc);
    u32 qh[2][2][4], ql[2][2][4];
#pragma unroll
    for (int mt = 0; mt < 2; ++mt)
#pragma unroll
        for (int nf = 0; nf < 4; ++nf) {
            int c = n0 + nf * 8 + 2 * (lane & 3);
            float2 b2 = __ldg((const float2*)(bq + c));
            float q0 = (acc[mt][nf][0] + b2.x) * QSCALE;
            float q1 = (acc[mt][nf][1] + b2.y) * QSCALE;
            float q2 = (acc[mt][nf][2] + b2.x) * QSCALE;
            float q3 = (acc[mt][nf][3] + b2.y) * QSCALE;
            int ks = nf >> 1, o = (nf & 1) * 2;
            qh[mt][ks][o] = pkbf(q0, q1);
            qh[mt][ks][o + 1] = pkbf(q2, q3);
            ql[mt][ks][o] = pkbf_lo(q0, q1, qh[mt][ks][o]);
            ql[mt][ks][o + 1] = pkbf_lo(q2, q3, qh[mt][ks][o + 1]);
        }
    __syncthreads();   // W1 (Wk) ready, W0 free

    // ======== phase B: Wv fill (W0) overlaps K gemm (W1) + scores ========
    fillW(sm + W0OFF, 2, tid);
    gemm32(smA, smW1, m0, n0, lane, acc);

    // K c-frags -> score B-frags in registers (+bk). kb[mt_k][tb][nf]:
    // t = m0 + mt_k*16 + tb*8 + lane>>2 ; d = n0 + nf*8 + (lane&3)*2.
    u32 kbh[2][2][4], kbl[2][2][4];
#pragma unroll
    for (int mt = 0; mt < 2; ++mt)
#pragma unroll
        for (int nf = 0; nf < 4; ++nf) {
            int c = n0 + nf * 8 + 2 * (lane & 3);
            float2 b2 = __ldg((const float2*)(bk + c));
            float v0 = acc[mt][nf][0] + b2.x, v1 = acc[mt][nf][1] + b2.y;
            float v2 = acc[mt][nf][2] + b2.x, v3 = acc[mt][nf][3] + b2.y;
            kbh[mt][0][nf] = pkbf(v0, v1);
            kbl[mt][0][nf] = pkbf_lo(v0, v1, kbh[mt][0][nf]);
            kbh[mt][1][nf] = pkbf(v2, v3);
            kbl[mt][1][nf] = pkbf_lo(v2, v3, kbh[mt][1][nf]);
        }

    // scores: S[mt_s][2*mt_k+tb] = Q @ K^T (k = d, 2 k16 steps), 3-term
    float S[2][4][4];
#pragma unroll
    for (int mt = 0; mt < 2; ++mt)
#pragma unroll
        for (int nf = 0; nf < 4; ++nf)
#pragma unroll
            for (int c = 0; c < 4; ++c) S[mt][nf][c] = 0.f;
#pragma unroll
    for (int ks = 0; ks < 2; ++ks) {
#pragma unroll
        for (int ms = 0; ms < 2; ++ms)
#pragma unroll
            for (int mk = 0; mk < 2; ++mk)
#pragma unroll
                for (int tb = 0; tb < 2; ++tb)
                    mma16816(S[ms][2 * mk + tb], qh[ms][ks],
                             kbh[mk][tb][2 * ks], kbh[mk][tb][2 * ks + 1]);
#pragma unroll
        for (int ms = 0; ms < 2; ++ms)
#pragma unroll
            for (int mk = 0; mk < 2; ++mk)
#pragma unroll
                for (int tb = 0; tb < 2; ++tb)
                    mma16816(S[ms][2 * mk + tb], ql[ms][ks],
                             kbh[mk][tb][2 * ks], kbh[mk][tb][2 * ks + 1]);
#pragma unroll
        for (int ms = 0; ms < 2; ++ms)
#pragma unroll
            for (int mk = 0; mk < 2; ++mk)
#pragma unroll
                for (int tb = 0; tb < 2; ++tb)
                    mma16816(S[ms][2 * mk + tb], qh[ms][ks],
                             kbl[mk][tb][2 * ks], kbl[mk][tb][2 * ks + 1]);
    }

    // softmax over t (row groups of 4 lanes) -> P a-frags
    u32 ph[2][2][4], pl[2][2][4];
    {
        float mx[2][2], iv[2][2];
#pragma unroll
        for (int mt = 0; mt < 2; ++mt)
#pragma unroll
            for (int hf = 0; hf < 2; ++hf) {
                float m = -1e30f;
#pragma unroll
                for (int nf = 0; nf < 4; ++nf)
                    m = fmaxf(m, fmaxf(S[mt][nf][hf * 2], S[mt][nf][hf * 2 + 1]));
                m = fmaxf(m, __shfl_xor_sync(~0u, m, 1));
                m = fmaxf(m, __shfl_xor_sync(~0u, m, 2));
                mx[mt][hf] = m;
            }
#pragma unroll
        for (int mt = 0; mt < 2; ++mt)
#pragma unroll
            for (int nf = 0; nf < 4; ++nf) {
                S[mt][nf][0] = __expf(S[mt][nf][0] - mx[mt][0]);
                S[mt][nf][1] = __expf(S[mt][nf][1] - mx[mt][0]);
                S[mt][nf][2] = __expf(S[mt][nf][2] - mx[mt][1]);
                S[mt][nf][3] = __expf(S[mt][nf][3] - mx[mt][1]);
            }
#pragma unroll
        for (int mt = 0; mt < 2; ++mt)
#pragma unroll
            for (int hf = 0; hf < 2; ++hf) {
                float s = 0.f;
#pragma unroll
                for (int nf = 0; nf < 4; ++nf)
                    s += S[mt][nf][hf * 2] + S[mt][nf][hf * 2 + 1];
                s += __shfl_xor_sync(~0u, s, 1);
                s += __shfl_xor_sync(~0u, s, 2);
                iv[mt][hf] = 1.f / s;
            }
#pragma unroll
        for (int mt = 0; mt < 2; ++mt)
#pragma unroll
            for (int nf = 0; nf < 4; ++nf) {
                float p0 = S[mt][nf][0] * iv[mt][0];
                float p1 = S[mt][nf][1] * iv[mt][0];
                float p2 = S[mt][nf][2] * iv[mt][1];
                float p3 = S[mt][nf][3] * iv[mt][1];
                int ks = nf >> 1, o = (nf & 1) * 2;
                ph[mt][ks][o] = pkbf(p0, p1);
                ph[mt][ks][o + 1] = pkbf(p2, p3);
                pl[mt][ks][o] = pkbf_lo(p0, p1, ph[mt][ks][o]);
                pl[mt][ks][o + 1] = pkbf_lo(p2, p3, ph[mt][ks][o + 1]);
            }
    }
    __syncthreads();   // W0 (Wv) ready, W1 free

    // ======== phase C: Wo fill (W1) overlaps V gemm (W0) + ctx ========
    fillW(sm + W1OFF, 3, tid);
    gemm32(smA, smW0, m0, n0, lane, acc);

    // V c-frags -> ctx B-frags via movmatrix transpose (+bv).
    // vb[kt][tb][nf]: transposed 8x8 block, t-block = kt*16 + tb*8, d-block nf.
    u32 vbh[2][2][4], vbl[2][2][4];
#pragma unroll
    for (int mt = 0; mt < 2; ++mt)
#pragma unroll
        for (int nf = 0; nf < 4; ++nf) {
            int c = n0 + nf * 8 + 2 * (lane & 3);
            float2 b2 = __ldg((const float2*)(bv + c));
            float v0 = acc[mt][nf][0] + b2.x, v1 = acc[mt][nf][1] + b2.y;
            float v2 = acc[mt][nf][2] + b2.x, v3 = acc[mt][nf][3] + b2.y;
            u32 h01 = pkbf(v0, v1), l01 = pkbf_lo(v0, v1, h01);
            u32 h23 = pkbf(v2, v3), l23 = pkbf_lo(v2, v3, h23);
            vbh[mt][0][nf] = movm_t(h01);
            vbl[mt][0][nf] = movm_t(l01);
            vbh[mt][1][nf] = movm_t(h23);
            vbl[mt][1][nf] = movm_t(l23);
        }

    // ctx C[mt_s][nf_d] = P @ V (k = t, 2 k16 steps), 3-term
    float C[2][4][4];
#pragma unroll
    for (int mt = 0; mt < 2; ++mt)
#pragma unroll
        for (int nf = 0; nf < 4; ++nf)
#pragma unroll
            for (int c = 0; c < 4; ++c) C[mt][nf][c] = 0.f;
#pragma unroll
    for (int kt = 0; kt < 2; ++kt) {
#pragma unroll
        for (int ms = 0; ms < 2; ++ms)
#pragma unroll
            for (int nf = 0; nf < 4; ++nf)
                mma16816(C[ms][nf], ph[ms][kt], vbh[kt][0][nf], vbh[kt][1][nf]);
#pragma unroll
        for (int ms = 0; ms < 2; ++ms)
#pragma unroll
            for (int nf = 0; nf < 4; ++nf)
                mma16816(C[ms][nf], pl[ms][kt], vbh[kt][0][nf], vbh[kt][1][nf]);
#pragma unroll
        for (int ms = 0; ms < 2; ++ms)
#pragma unroll
            for (int nf = 0; nf < 4; ++nf)
                mma16816(C[ms][nf], ph[ms][kt], vbl[kt][0][nf], vbl[kt][1][nf]);
    }

    __syncthreads();   // all warps done reading A (V gemm)
    // ctx -> A tile (bf16 hi/lo) at rows m0.., cols h*32..
    store_split(sm + AOFF, C, m0, n0, lane);
    __syncthreads();   // ctx in A + W1 (Wo) ready

    // ======== phase D: out projection + epilogue ========
    gemm32(smA, smW1, m0, n0, lane, acc);

    {
        float s1[2][2] = {{0.f, 0.f}, {0.f, 0.f}};
        float s2[2][2] = {{0.f, 0.f}, {0.f, 0.f}};
#pragma unroll
        for (int mt = 0; mt < 2; ++mt) {
            int r = m0 + mt * 16 + (lane >> 2);
#pragma unroll
            for (int nf = 0; nf < 4; ++nf) {
                int c = n0 + nf * 8 + 2 * (lane & 3);
                float2 b2 = __ldg((const float2*)(bo + c));
                float2 xa = __ldg((const float2*)(inputs + tbase + (size_t)r * 128 + c));
                float2 xb = __ldg((const float2*)(inputs + tbase + (size_t)(r + 8) * 128 + c));
                acc[mt][nf][0] += b2.x + xa.x; acc[mt][nf][1] += b2.y + xa.y;
                acc[mt][nf][2] += b2.x + xb.x; acc[mt][nf][3] += b2.y + xb.y;
                s1[mt][0] += acc[mt][nf][0] + acc[mt][nf][1];
                s2[mt][0] += acc[mt][nf][0] * acc[mt][nf][0] + acc[mt][nf][1] * acc[mt][nf][1];
                s1[mt][1] += acc[mt][nf][2] + acc[mt][nf][3];
                s2[mt][1] += acc[mt][nf][2] * acc[mt][nf][2] + acc[mt][nf][3] * acc[mt][nf][3];
            }
        }
#pragma unroll
        for (int mt = 0; mt < 2; ++mt)
#pragma unroll
            for (int hf = 0; hf < 2; ++hf) {
                s1[mt][hf] += __shfl_xor_sync(~0u, s1[mt][hf], 1);
                s1[mt][hf] += __shfl_xor_sync(~0u, s1[mt][hf], 2);
                s2[mt][hf] += __shfl_xor_sync(~0u, s2[mt][hf], 1);
                s2[mt][hf] += __shfl_xor_sync(~0u, s2[mt][hf], 2);
            }
        float2* part = (float2*)(sm + POFF);
        if ((lane & 3) == 0) {
#pragma unroll
            for (int mt = 0; mt < 2; ++mt) {
                int r = m0 + mt * 16 + (lane >> 2);
                part[r * 4 + h] = make_float2(s1[mt][0], s2[mt][0]);
                part[(r + 8) * 4 + h] = make_float2(s1[mt][1], s2[mt][1]);
            }
        }
        __syncthreads();
        float mu[2][2], rs[2][2];
#pragma unroll
        for (int mt = 0; mt < 2; ++mt)
#pragma unroll
            for (int hf = 0; hf < 2; ++hf) {
                int r = m0 + mt * 16 + (lane >> 2) + hf * 8;
                float2 p0 = part[r * 4 + 0], p1 = part[r * 4 + 1];
                float2 p2 = part[r * 4 + 2], p3 = part[r * 4 + 3];
                float S1 = p0.x + p1.x + p2.x + p3.x;
                float S2 = p0.y + p1.y + p2.y + p3.y;
                float m = S1 * (1.f / 128.f);
                float v = S2 * (1.f / 128.f) - m * m;
                mu[mt][hf] = m;
                rs[mt][hf] = rsqrtf(v + 1e-5f);
            }
#pragma unroll
        for (int mt = 0; mt < 2; ++mt) {
            int r = m0 + mt * 16 + (lane >> 2);
#pragma unroll
            for (int nf = 0; nf < 4; ++nf) {
                int c = n0 + nf * 8 + 2 * (lane & 3);
                float2 g2 = __ldg((const float2*)(gamma + c));
                float2 e2 = __ldg((const float2*)(beta + c));
                float2 o1, o2;
                o1.x = (acc[mt][nf][0] - mu[mt][0]) * rs[mt][0] * g2.x + e2.x;
                o1.y = (acc[mt][nf][1] - mu[mt][0]) * rs[mt][0] * g2.y + e2.y;
                o2.x = (acc[mt][nf][2] - mu[mt][1]) * rs[mt][1] * g2.x + e2.x;
                o2.y = (acc[mt][nf][3] - mu[mt][1]) * rs[mt][1] * g2.y + e2.y;
                *(float2*)(outp + tbase + (size_t)r * 128 + c) = o1;
                *(float2*)(outp + tbase + (size_t)(r + 8) * 128 + c) = o2;
            }
        }
    }
}

extern "C" void kernel_launch(void* const* d_in, const int* in_sizes, int n_in,
                              void* d_out, int out_size) {
    const float* inputs = (const float*)d_in[0];
    const float* Wq = (const float*)d_in[1];
    const float* bq = (const float*)d_in[2];
    const float* Wk = (const float*)d_in[3];
    const float* bk = (const float*)d_in[4];
    const float* Wv = (const float*)d_in[5];
    const float* bv = (const float*)d_in[6];
    const float* Wo = (const float*)d_in[7];
    const float* bo = (const float*)d_in[8];
    const float* gamma = (const float*)d_in[9];
    const float* beta  = (const float*)d_in[10];
    float* outp = (float*)d_out;

    prep_split<<<256, 256>>>(Wq, Wk, Wv, Wo);

    int grid = in_sizes[0] / 16384;   // 128 rows * 128 cols per CTA
    cudaFuncSetAttribute(fused_attn_fa,
                         cudaFuncAttributeMaxDynamicSharedMemorySize, SMEM_BYTES);
    fused_attn_fa<<<grid, NT, SMEM_BYTES>>>(inputs, bq, bk, bv, bo, gamma, beta, outp);
}